// round 1
// baseline (speedup 1.0000x reference)
#include <cuda_runtime.h>

// Problem constants
// x: (4, 4096, 1024) fp32; wq/wk/wv/wo: (1024, 1024) fp32 (out, in) -> y = x @ W^T
#define NTOK   16384      // 4 * 4096 tokens
#define HID    1024
#define NHEADS 16
#define HDIM   64

// Scratch (no cudaMalloc allowed): 4 x 64MB fp32
__device__ float g_q[NTOK * HID];
__device__ float g_k[NTOK * HID];
__device__ float g_v[NTOK * HID];
__device__ float g_a[NTOK * HID];

// ---------------------------------------------------------------------------
// SGEMM: C[M,N] = A[M,K] @ B[N,K]^T   (both A and B K-contiguous, row-major)
// M=16384, N=1024, K=1024. Tile 128x128x16, 256 threads, 8x8 per thread.
// ---------------------------------------------------------------------------
__device__ __forceinline__ void gemm_body(const float* __restrict__ A,
                                          const float* __restrict__ B,
                                          float* __restrict__ C)
{
    constexpr int K = 1024, N = 1024;
    constexpr int BM = 128, BN = 128, BK = 16;

    __shared__ float As[BK][BM + 4];   // transposed tiles; row stride 132 floats (16B aligned)
    __shared__ float Bs[BK][BN + 4];

    const int tid = threadIdx.x;
    const int bm = blockIdx.y * BM;
    const int bn = blockIdx.x * BN;
    const int ty = tid >> 4;          // 0..15
    const int tx = tid & 15;          // 0..15

    float acc[8][8];
#pragma unroll
    for (int i = 0; i < 8; ++i)
#pragma unroll
        for (int j = 0; j < 8; ++j) acc[i][j] = 0.f;

    for (int k0 = 0; k0 < K; k0 += BK) {
        // Load A,B tiles: 128 rows x 16 k each = 512 float4 per tile; 2 slots/thread.
#pragma unroll
        for (int t = 0; t < 2; ++t) {
            const int slot = tid + t * 256;
            const int row  = slot >> 2;            // 0..127
            const int kc   = (slot & 3) * 4;       // 0,4,8,12
            const float4 va = *(const float4*)&A[(size_t)(bm + row) * K + k0 + kc];
            As[kc + 0][row] = va.x; As[kc + 1][row] = va.y;
            As[kc + 2][row] = va.z; As[kc + 3][row] = va.w;
            const float4 vb = *(const float4*)&B[(size_t)(bn + row) * K + k0 + kc];
            Bs[kc + 0][row] = vb.x; Bs[kc + 1][row] = vb.y;
            Bs[kc + 2][row] = vb.z; Bs[kc + 3][row] = vb.w;
        }
        __syncthreads();

#pragma unroll
        for (int k = 0; k < BK; ++k) {
            const float4 a0 = *(const float4*)&As[k][ty * 8];
            const float4 a1 = *(const float4*)&As[k][ty * 8 + 4];
            const float4 b0 = *(const float4*)&Bs[k][tx * 8];
            const float4 b1 = *(const float4*)&Bs[k][tx * 8 + 4];
            const float a[8] = {a0.x, a0.y, a0.z, a0.w, a1.x, a1.y, a1.z, a1.w};
            const float b[8] = {b0.x, b0.y, b0.z, b0.w, b1.x, b1.y, b1.z, b1.w};
#pragma unroll
            for (int i = 0; i < 8; ++i)
#pragma unroll
                for (int j = 0; j < 8; ++j)
                    acc[i][j] = fmaf(a[i], b[j], acc[i][j]);
        }
        __syncthreads();
    }

#pragma unroll
    for (int i = 0; i < 8; ++i) {
        const size_t row = (size_t)(bm + ty * 8 + i);
        float4 v0 = {acc[i][0], acc[i][1], acc[i][2], acc[i][3]};
        float4 v1 = {acc[i][4], acc[i][5], acc[i][6], acc[i][7]};
        *(float4*)&C[row * N + bn + tx * 8]     = v0;
        *(float4*)&C[row * N + bn + tx * 8 + 4] = v1;
    }
}

// QKV: blockIdx.z picks the weight + destination (fused 3-way GEMM launch)
__global__ __launch_bounds__(256) void qkv_gemm(const float* __restrict__ X,
                                                const float* __restrict__ Wq,
                                                const float* __restrict__ Wk,
                                                const float* __restrict__ Wv)
{
    const float* W;
    float* O;
    if (blockIdx.z == 0)      { W = Wq; O = g_q; }
    else if (blockIdx.z == 1) { W = Wk; O = g_k; }
    else                      { W = Wv; O = g_v; }
    gemm_body(X, W, O);
}

__global__ __launch_bounds__(256) void o_gemm(const float* __restrict__ Wo,
                                              float* __restrict__ Out)
{
    gemm_body(g_a, Wo, Out);
}

// ---------------------------------------------------------------------------
// Per-token attention over heads:
//   scores[h][g] = q[h]·k[g] / sqrt(64); softmax over g; out[h] = sum_g p * v[g]
// One block (256 threads) per token.
// ---------------------------------------------------------------------------
__global__ __launch_bounds__(256) void attn_kernel()
{
    __shared__ float sq[16][68];   // pad 68: 16B-aligned rows, conflict-spread
    __shared__ float sk[16][68];
    __shared__ float sv[16][68];
    __shared__ float sp[16][17];

    const int t   = blockIdx.x;
    const int tid = threadIdx.x;
    const size_t base = (size_t)t * HID;

    // Stage q,k,v for this token (1024 floats each = 256 float4)
    {
        const int row = tid >> 4;            // head 0..15
        const int col = (tid & 15) * 4;      // 0..60
        *(float4*)&sq[row][col] = *(const float4*)&g_q[base + row * HDIM + col];
        *(float4*)&sk[row][col] = *(const float4*)&g_k[base + row * HDIM + col];
        *(float4*)&sv[row][col] = *(const float4*)&g_v[base + row * HDIM + col];
    }
    __syncthreads();

    const int h = tid >> 4;
    const int g = tid & 15;

    float s = 0.f;
#pragma unroll
    for (int d = 0; d < HDIM; ++d) s = fmaf(sq[h][d], sk[g][d], s);
    s *= 0.125f;   // 1/sqrt(64)

    // Row softmax across the 16 consecutive lanes holding one h-row
    float m = s;
#pragma unroll
    for (int off = 8; off; off >>= 1)
        m = fmaxf(m, __shfl_xor_sync(0xffffffffu, m, off, 16));
    const float e = __expf(s - m);
    float sum = e;
#pragma unroll
    for (int off = 8; off; off >>= 1)
        sum += __shfl_xor_sync(0xffffffffu, sum, off, 16);
    sp[h][g] = e / sum;
    __syncthreads();

    // out[h][d0..d0+3] = sum_g p[h][g] * v[g][d0..d0+3]
    const int d0 = (tid & 15) * 4;
    float4 o = {0.f, 0.f, 0.f, 0.f};
#pragma unroll
    for (int gg = 0; gg < 16; ++gg) {
        const float p = sp[h][gg];
        o.x = fmaf(p, sv[gg][d0 + 0], o.x);
        o.y = fmaf(p, sv[gg][d0 + 1], o.y);
        o.z = fmaf(p, sv[gg][d0 + 2], o.z);
        o.w = fmaf(p, sv[gg][d0 + 3], o.w);
    }
    *(float4*)&g_a[base + h * HDIM + d0] = o;
}

// ---------------------------------------------------------------------------
extern "C" void kernel_launch(void* const* d_in, const int* in_sizes, int n_in,
                              void* d_out, int out_size)
{
    const float* x  = (const float*)d_in[0];
    const float* wq = (const float*)d_in[1];
    const float* wk = (const float*)d_in[2];
    const float* wv = (const float*)d_in[3];
    const float* wo = (const float*)d_in[4];
    float* out = (float*)d_out;

    dim3 gqkv(HID / 128, NTOK / 128, 3);   // (8, 128, 3)
    qkv_gemm<<<gqkv, 256>>>(x, wq, wk, wv);

    attn_kernel<<<NTOK, 256>>>();

    dim3 go(HID / 128, NTOK / 128, 1);     // (8, 128, 1)
    o_gemm<<<go, 256>>>(wo, out);
}

// round 4
// speedup vs baseline: 2.3082x; 2.3082x over previous
#include <cuda_runtime.h>
#include <cuda_bf16.h>
#include <cstdint>

#define NTOK   16384
#define HID    1024
#define HDIM   64

// ---------------- scratch (device globals; no cudaMalloc allowed) -------------
__device__ __align__(256) __nv_bfloat16 g_xh[NTOK * HID];
__device__ __align__(256) __nv_bfloat16 g_xl[NTOK * HID];
__device__ __align__(256) __nv_bfloat16 g_wh[4 * HID * HID];
__device__ __align__(256) __nv_bfloat16 g_wl[4 * HID * HID];
__device__ __align__(256) float g_q[NTOK * HID];
__device__ __align__(256) float g_k[NTOK * HID];
__device__ __align__(256) float g_v[NTOK * HID];
__device__ __align__(256) __nv_bfloat16 g_ah[NTOK * HID];
__device__ __align__(256) __nv_bfloat16 g_al[NTOK * HID];

// ---------------- PTX helpers (all plain-sm_103-legal) ------------------------
__device__ __forceinline__ uint32_t smem_u32(const void* p) {
    uint32_t a;
    asm("{ .reg .u64 t; cvta.to.shared.u64 t, %1; cvt.u32.u64 %0, t; }" : "=r"(a) : "l"(p));
    return a;
}

__device__ __forceinline__ void cp_async16(uint32_t saddr, const void* gptr) {
    asm volatile("cp.async.cg.shared.global [%0], [%1], 16;"
                 :: "r"(saddr), "l"(__cvta_generic_to_global(gptr)) : "memory");
}
__device__ __forceinline__ void cp_commit() {
    asm volatile("cp.async.commit_group;" ::: "memory");
}
template <int N>
__device__ __forceinline__ void cp_wait() {
    asm volatile("cp.async.wait_group %0;" :: "n"(N) : "memory");
}

__device__ __forceinline__ void ldsm4(uint32_t addr, uint32_t* r) {
    asm volatile("ldmatrix.sync.aligned.m8n8.x4.shared.b16 {%0,%1,%2,%3}, [%4];"
                 : "=r"(r[0]), "=r"(r[1]), "=r"(r[2]), "=r"(r[3]) : "r"(addr));
}

// D += A * B  (m16n8k16, bf16 in, fp32 acc)
__device__ __forceinline__ void mma_bf16(float* c, const uint32_t* a, const uint32_t* b) {
    asm volatile("mma.sync.aligned.m16n8k16.row.col.f32.bf16.bf16.f32 "
                 "{%0,%1,%2,%3}, {%4,%5,%6,%7}, {%8,%9}, {%0,%1,%2,%3};"
                 : "+f"(c[0]), "+f"(c[1]), "+f"(c[2]), "+f"(c[3])
                 : "r"(a[0]), "r"(a[1]), "r"(a[2]), "r"(a[3]), "r"(b[0]), "r"(b[1]));
}

// ---------------- smem layout ------------------------------------------------
// 3 pipeline slots, 32KB each:
//   A tile at +0:     128 rows x 128B  (row = [Ah 64B | Al 64B], 32 bf16 each)
//   B tile at +16384: 128 rows x 128B  (row = [Bh 64B | Bl 64B])
// XOR swizzle: bo ^ ((row&7)<<4)  -> conflict-free 16B-granular ldmatrix.
#define SLOT_BYTES 32768
#define NSLOTS     3
#define SMEM_BYTES (NSLOTS * SLOT_BYTES)

// ldmatrix.x4 address for a m16/n16 x k16 fragment.
// base: tile base; R: first row (16-row group); kb: byte offset of k16 within 128B row.
__device__ __forceinline__ uint32_t frag_addr(uint32_t base, int R, int kb, int lane) {
    const int row = R + (lane & 7) + ((lane >> 3) & 1) * 8;
    const int kc  = kb + (lane >> 4) * 16;
    const uint32_t bo = (uint32_t)(row * 128 + kc);
    return base + (bo ^ (uint32_t)((row & 7) << 4));
}

__device__ __forceinline__ void load_stage(uint32_t slot_base,
                                           const __nv_bfloat16* __restrict__ Ah,
                                           const __nv_bfloat16* __restrict__ Al,
                                           const __nv_bfloat16* __restrict__ Bh,
                                           const __nv_bfloat16* __restrict__ Bl,
                                           int k0, int tid)
{
    const uint32_t sA = slot_base;
    const uint32_t sB = slot_base + 16384;
#pragma unroll
    for (int j = 0; j < 4; ++j) {
        const int id   = tid + j * 256;       // 0..1023
        const int row  = id >> 3;             // 0..127
        const int ci   = id & 7;              // 0..7
        const int half = ci >> 2;             // 0 = hi, 1 = lo
        const int c    = ci & 3;              // 16B chunk within 64B half
        const uint32_t bo = (uint32_t)(row * 128 + half * 64 + c * 16);
        const uint32_t sw = bo ^ (uint32_t)((row & 7) << 4);
        const size_t goff = (size_t)row * HID + k0 + c * 8;
        cp_async16(sA + sw, (half ? Al : Ah) + goff);
        cp_async16(sB + sw, (half ? Bl : Bh) + goff);
    }
    cp_commit();
}

// ---------------- split-bf16 tensor-core GEMM --------------------------------
// C[M,1024] = Ah*Bh^T + Ah*Bl^T + Al*Bh^T   (A:[M,1024], B:[1024,1024], K-contig)
__device__ __forceinline__ void gemm_tc(const __nv_bfloat16* __restrict__ Ah,
                                        const __nv_bfloat16* __restrict__ Al,
                                        const __nv_bfloat16* __restrict__ Bh,
                                        const __nv_bfloat16* __restrict__ Bl,
                                        float* __restrict__ C)
{
    extern __shared__ char smem[];
    const uint32_t sbase = smem_u32(smem);
    const int tid  = threadIdx.x;
    const int wid  = tid >> 5;
    const int lane = tid & 31;
    const int bm   = blockIdx.y * 128;
    const int bn   = blockIdx.x * 128;
    const int wm   = (wid >> 2) * 64;   // warp M offset (0 or 64)
    const int wn   = (wid & 3) * 32;    // warp N offset (0,32,64,96)

    const __nv_bfloat16* Ahb = Ah + (size_t)bm * HID;
    const __nv_bfloat16* Alb = Al + (size_t)bm * HID;
    const __nv_bfloat16* Bhb = Bh + (size_t)bn * HID;
    const __nv_bfloat16* Blb = Bl + (size_t)bn * HID;

    float acc[4][4][4];
#pragma unroll
    for (int i = 0; i < 4; ++i)
#pragma unroll
        for (int j = 0; j < 4; ++j)
#pragma unroll
            for (int r = 0; r < 4; ++r) acc[i][j][r] = 0.f;

    // prologue: stages 0,1 into slots 0,1
    load_stage(sbase,              Ahb, Alb, Bhb, Blb,  0, tid);
    load_stage(sbase + SLOT_BYTES, Ahb, Alb, Bhb, Blb, 32, tid);

#pragma unroll 1
    for (int t = 0; t < 32; ++t) {
        if (t < 31) cp_wait<1>(); else cp_wait<0>();
        __syncthreads();

        // prefetch stage t+2 into slot (t+2)%3 (consumed at t-1; sync above covers it)
        if (t + 2 < 32) {
            const int slot = (t + 2) % NSLOTS;
            load_stage(sbase + slot * SLOT_BYTES, Ahb, Alb, Bhb, Blb, (t + 2) * 32, tid);
        }

        const uint32_t sA = sbase + (t % NSLOTS) * SLOT_BYTES;
        const uint32_t sB = sA + 16384;

#pragma unroll
        for (int s = 0; s < 2; ++s) {          // two k16 steps in BK=32
            const int kb = s * 32;
            // B fragments for this warp's n=32 strip (hi and lo)
            uint32_t bh[4][2], bl[4][2];
#pragma unroll
            for (int p = 0; p < 2; ++p) {
                uint32_t r[4];
                ldsm4(frag_addr(sB, wn + p * 16, kb, lane), r);
                bh[2 * p][0] = r[0]; bh[2 * p + 1][0] = r[1];
                bh[2 * p][1] = r[2]; bh[2 * p + 1][1] = r[3];
                ldsm4(frag_addr(sB, wn + p * 16, 64 + kb, lane), r);
                bl[2 * p][0] = r[0]; bl[2 * p + 1][0] = r[1];
                bl[2 * p][1] = r[2]; bl[2 * p + 1][1] = r[3];
            }
#pragma unroll
            for (int fm = 0; fm < 4; ++fm) {
                uint32_t ah[4], al[4];
                ldsm4(frag_addr(sA, wm + fm * 16, kb, lane), ah);
                ldsm4(frag_addr(sA, wm + fm * 16, 64 + kb, lane), al);
#pragma unroll
                for (int fn = 0; fn < 4; ++fn) {
                    mma_bf16(acc[fm][fn], ah, bh[fn]);
                    mma_bf16(acc[fm][fn], ah, bl[fn]);
                    mma_bf16(acc[fm][fn], al, bh[fn]);
                }
            }
        }
    }

    // epilogue: register fragments -> gmem (float2 per row-segment)
#pragma unroll
    for (int fm = 0; fm < 4; ++fm) {
        const int r0 = bm + wm + fm * 16 + (lane >> 2);
#pragma unroll
        for (int fn = 0; fn < 4; ++fn) {
            const int c0 = bn + wn + fn * 8 + (lane & 3) * 2;
            float2 v0 = { acc[fm][fn][0], acc[fm][fn][1] };
            float2 v1 = { acc[fm][fn][2], acc[fm][fn][3] };
            *(float2*)&C[(size_t)r0 * HID + c0]       = v0;
            *(float2*)&C[(size_t)(r0 + 8) * HID + c0] = v1;
        }
    }
}

__global__ void __launch_bounds__(256, 2) tc_qkv() {
    const size_t woff = (size_t)blockIdx.z * HID * HID;
    float* C = (blockIdx.z == 0) ? g_q : (blockIdx.z == 1) ? g_k : g_v;
    gemm_tc(g_xh, g_xl, g_wh + woff, g_wl + woff, C);
}

__global__ void __launch_bounds__(256, 2) tc_o(float* __restrict__ out) {
    gemm_tc(g_ah, g_al, g_wh + (size_t)3 * HID * HID, g_wl + (size_t)3 * HID * HID, out);
}

// ---------------- fp32 -> split bf16 conversion ------------------------------
__global__ void __launch_bounds__(256) conv_x(const float* __restrict__ x) {
    const size_t i = (size_t)blockIdx.x * 256 + threadIdx.x;
    const float4 v = ((const float4*)x)[i];
    float f[4] = { v.x, v.y, v.z, v.w };
    __nv_bfloat16 h[4], l[4];
#pragma unroll
    for (int j = 0; j < 4; ++j) {
        h[j] = __float2bfloat16(f[j]);
        l[j] = __float2bfloat16(f[j] - __bfloat162float(h[j]));
    }
    *(uint2*)(g_xh + i * 4) = *(const uint2*)h;
    *(uint2*)(g_xl + i * 4) = *(const uint2*)l;
}

__global__ void __launch_bounds__(256) conv_w(const float* __restrict__ wq,
                                              const float* __restrict__ wk,
                                              const float* __restrict__ wv,
                                              const float* __restrict__ wo) {
    const float* w = (blockIdx.y == 0) ? wq : (blockIdx.y == 1) ? wk
                   : (blockIdx.y == 2) ? wv : wo;
    const size_t i = (size_t)blockIdx.x * 256 + threadIdx.x;
    const float4 v = ((const float4*)w)[i];
    float f[4] = { v.x, v.y, v.z, v.w };
    __nv_bfloat16 h[4], l[4];
#pragma unroll
    for (int j = 0; j < 4; ++j) {
        h[j] = __float2bfloat16(f[j]);
        l[j] = __float2bfloat16(f[j] - __bfloat162float(h[j]));
    }
    const size_t base = (size_t)blockIdx.y * HID * HID + i * 4;
    *(uint2*)(g_wh + base) = *(const uint2*)h;
    *(uint2*)(g_wl + base) = *(const uint2*)l;
}

// ---------------- per-token attention over heads (fp32) ----------------------
__global__ void __launch_bounds__(256) attn_kernel() {
    __shared__ float sq[16][68];
    __shared__ float sk[16][68];
    __shared__ float sv[16][68];
    __shared__ float sp[16][17];

    const int t   = blockIdx.x;
    const int tid = threadIdx.x;
    const size_t base = (size_t)t * HID;

    {
        const int row = tid >> 4;
        const int col = (tid & 15) * 4;
        *(float4*)&sq[row][col] = *(const float4*)&g_q[base + row * HDIM + col];
        *(float4*)&sk[row][col] = *(const float4*)&g_k[base + row * HDIM + col];
        *(float4*)&sv[row][col] = *(const float4*)&g_v[base + row * HDIM + col];
    }
    __syncthreads();

    const int h = tid >> 4;
    const int g = tid & 15;

    float s = 0.f;
#pragma unroll
    for (int d = 0; d < HDIM; ++d) s = fmaf(sq[h][d], sk[g][d], s);
    s *= 0.125f;

    float m = s;
#pragma unroll
    for (int off = 8; off; off >>= 1)
        m = fmaxf(m, __shfl_xor_sync(0xffffffffu, m, off, 16));
    const float e = __expf(s - m);
    float sum = e;
#pragma unroll
    for (int off = 8; off; off >>= 1)
        sum += __shfl_xor_sync(0xffffffffu, sum, off, 16);
    sp[h][g] = e / sum;
    __syncthreads();

    const int d0 = (tid & 15) * 4;
    float4 o = { 0.f, 0.f, 0.f, 0.f };
#pragma unroll
    for (int gg = 0; gg < 16; ++gg) {
        const float p = sp[h][gg];
        o.x = fmaf(p, sv[gg][d0 + 0], o.x);
        o.y = fmaf(p, sv[gg][d0 + 1], o.y);
        o.z = fmaf(p, sv[gg][d0 + 2], o.z);
        o.w = fmaf(p, sv[gg][d0 + 3], o.w);
    }

    // split to bf16 hi/lo for the O-projection tensor GEMM
    const size_t oidx = base + h * HDIM + d0;
    float f[4] = { o.x, o.y, o.z, o.w };
    __nv_bfloat16 hh[4], ll[4];
#pragma unroll
    for (int j = 0; j < 4; ++j) {
        hh[j] = __float2bfloat16(f[j]);
        ll[j] = __float2bfloat16(f[j] - __bfloat162float(hh[j]));
    }
    *(uint2*)(g_ah + oidx) = *(const uint2*)hh;
    *(uint2*)(g_al + oidx) = *(const uint2*)ll;
}

// ---------------------------------------------------------------------------
extern "C" void kernel_launch(void* const* d_in, const int* in_sizes, int n_in,
                              void* d_out, int out_size)
{
    const float* x  = (const float*)d_in[0];
    const float* wq = (const float*)d_in[1];
    const float* wk = (const float*)d_in[2];
    const float* wv = (const float*)d_in[3];
    const float* wo = (const float*)d_in[4];
    float* out = (float*)d_out;

    cudaFuncSetAttribute(tc_qkv, cudaFuncAttributeMaxDynamicSharedMemorySize, SMEM_BYTES);
    cudaFuncSetAttribute(tc_o,   cudaFuncAttributeMaxDynamicSharedMemorySize, SMEM_BYTES);

    conv_x<<<NTOK * HID / 4 / 256, 256>>>(x);
    conv_w<<<dim3(HID * HID / 4 / 256, 4), 256>>>(wq, wk, wv, wo);

    dim3 gqkv(HID / 128, NTOK / 128, 3);
    tc_qkv<<<gqkv, 256, SMEM_BYTES>>>();

    attn_kernel<<<NTOK, 256>>>();

    dim3 go(HID / 128, NTOK / 128, 1);
    tc_o<<<go, 256, SMEM_BYTES>>>(out);
}

// round 5
// speedup vs baseline: 5.7566x; 2.4939x over previous
#include <cuda_runtime.h>
#include <cuda_fp16.h>
#include <cstdint>

#define NTOK   16384
#define HID    1024
#define HDIM   64

// ---------------- scratch (device globals; no cudaMalloc allowed) -------------
__device__ __align__(256) __half g_xh[NTOK * HID];
__device__ __align__(256) __half g_wh[4 * HID * HID];
__device__ __align__(256) float  g_q[NTOK * HID];
__device__ __align__(256) float  g_k[NTOK * HID];
__device__ __align__(256) float  g_v[NTOK * HID];
__device__ __align__(256) __half g_ah[NTOK * HID];

// ---------------- PTX helpers (plain-sm_103-legal) -----------------------------
__device__ __forceinline__ uint32_t smem_u32(const void* p) {
    uint32_t a;
    asm("{ .reg .u64 t; cvta.to.shared.u64 t, %1; cvt.u32.u64 %0, t; }" : "=r"(a) : "l"(p));
    return a;
}

__device__ __forceinline__ void cp_async16(uint32_t saddr, const void* gptr) {
    asm volatile("cp.async.cg.shared.global [%0], [%1], 16;"
                 :: "r"(saddr), "l"(__cvta_generic_to_global(gptr)) : "memory");
}
__device__ __forceinline__ void cp_commit() {
    asm volatile("cp.async.commit_group;" ::: "memory");
}
template <int N>
__device__ __forceinline__ void cp_wait() {
    asm volatile("cp.async.wait_group %0;" :: "n"(N) : "memory");
}

__device__ __forceinline__ void ldsm4(uint32_t addr, uint32_t* r) {
    asm volatile("ldmatrix.sync.aligned.m8n8.x4.shared.b16 {%0,%1,%2,%3}, [%4];"
                 : "=r"(r[0]), "=r"(r[1]), "=r"(r[2]), "=r"(r[3]) : "r"(addr));
}

// D += A * B  (m16n8k16, fp16 in, fp32 acc)
__device__ __forceinline__ void mma_fp16(float* c, const uint32_t* a, const uint32_t* b) {
    asm volatile("mma.sync.aligned.m16n8k16.row.col.f32.f16.f16.f32 "
                 "{%0,%1,%2,%3}, {%4,%5,%6,%7}, {%8,%9}, {%0,%1,%2,%3};"
                 : "+f"(c[0]), "+f"(c[1]), "+f"(c[2]), "+f"(c[3])
                 : "r"(a[0]), "r"(a[1]), "r"(a[2]), "r"(a[3]), "r"(b[0]), "r"(b[1]));
}

// ---------------- smem layout ------------------------------------------------
// 3 pipeline slots, 32KB each: A tile (128 rows x 64 fp16 = 128B rows, 16KB)
// then B tile (16KB). XOR swizzle: bo ^ ((row&7)<<4) -> conflict-free ldmatrix.
#define BK         64
#define TILE_BYTES 16384
#define SLOT_BYTES 32768
#define NSLOTS     3
#define SMEM_BYTES (NSLOTS * SLOT_BYTES)
#define NSTAGES    (HID / BK)     // 16

// ldmatrix.x4 address: R = first row of 16-row group, kb = byte offset of k16 chunk
__device__ __forceinline__ uint32_t frag_addr(uint32_t base, int R, int kb, int lane) {
    const int row = R + (lane & 7) + ((lane >> 3) & 1) * 8;
    const int kc  = kb + (lane >> 4) * 16;
    const uint32_t bo = (uint32_t)(row * 128 + kc);
    return base + (bo ^ (uint32_t)((row & 7) << 4));
}

__device__ __forceinline__ void load_stage(uint32_t slot_base,
                                           const __half* __restrict__ A,
                                           const __half* __restrict__ B,
                                           int k0, int tid)
{
#pragma unroll
    for (int j = 0; j < 4; ++j) {
        const int id  = tid + j * 256;          // 0..1023 chunks of 16B
        const int row = id >> 3;                // 0..127
        const int c   = id & 7;                 // 16B chunk within 128B row
        const uint32_t bo = (uint32_t)(row * 128 + c * 16);
        const uint32_t sw = bo ^ (uint32_t)((row & 7) << 4);
        const size_t goff = (size_t)row * HID + k0 + c * 8;
        cp_async16(slot_base + sw, A + goff);
        cp_async16(slot_base + TILE_BYTES + sw, B + goff);
    }
    cp_commit();
}

// ---------------- fp16 tensor-core GEMM --------------------------------------
// C[M,1024] = A[M,1024] @ B[1024,1024]^T  (fp16 in, fp32 acc; both K-contiguous)
__device__ __forceinline__ void gemm_tc(const __half* __restrict__ A,
                                        const __half* __restrict__ B,
                                        float* __restrict__ C)
{
    extern __shared__ char smem[];
    const uint32_t sbase = smem_u32(smem);
    const int tid  = threadIdx.x;
    const int wid  = tid >> 5;
    const int lane = tid & 31;
    const int bm   = blockIdx.y * 128;
    const int bn   = blockIdx.x * 128;
    const int wm   = (wid >> 2) * 64;   // warp M offset (0 or 64)
    const int wn   = (wid & 3) * 32;    // warp N offset (0,32,64,96)

    const __half* Ab = A + (size_t)bm * HID;
    const __half* Bb = B + (size_t)bn * HID;

    float acc[4][4][4];
#pragma unroll
    for (int i = 0; i < 4; ++i)
#pragma unroll
        for (int j = 0; j < 4; ++j)
#pragma unroll
            for (int r = 0; r < 4; ++r) acc[i][j][r] = 0.f;

    load_stage(sbase,              Ab, Bb, 0,  tid);
    load_stage(sbase + SLOT_BYTES, Ab, Bb, BK, tid);

#pragma unroll 1
    for (int t = 0; t < NSTAGES; ++t) {
        if (t < NSTAGES - 1) cp_wait<1>(); else cp_wait<0>();
        __syncthreads();

        if (t + 2 < NSTAGES) {
            const int slot = (t + 2) % NSLOTS;
            load_stage(sbase + slot * SLOT_BYTES, Ab, Bb, (t + 2) * BK, tid);
        }

        const uint32_t sA = sbase + (t % NSLOTS) * SLOT_BYTES;
        const uint32_t sB = sA + TILE_BYTES;

#pragma unroll
        for (int s = 0; s < BK / 16; ++s) {      // 4 k16 steps
            const int kb = s * 32;
            uint32_t b[4][2];
#pragma unroll
            for (int p = 0; p < 2; ++p) {
                uint32_t r[4];
                ldsm4(frag_addr(sB, wn + p * 16, kb, lane), r);
                b[2 * p][0] = r[0]; b[2 * p + 1][0] = r[1];
                b[2 * p][1] = r[2]; b[2 * p + 1][1] = r[3];
            }
#pragma unroll
            for (int fm = 0; fm < 4; ++fm) {
                uint32_t a[4];
                ldsm4(frag_addr(sA, wm + fm * 16, kb, lane), a);
#pragma unroll
                for (int fn = 0; fn < 4; ++fn)
                    mma_fp16(acc[fm][fn], a, b[fn]);
            }
        }
    }

    // epilogue: register fragments -> gmem
#pragma unroll
    for (int fm = 0; fm < 4; ++fm) {
        const int r0 = bm + wm + fm * 16 + (lane >> 2);
#pragma unroll
        for (int fn = 0; fn < 4; ++fn) {
            const int c0 = bn + wn + fn * 8 + (lane & 3) * 2;
            float2 v0 = { acc[fm][fn][0], acc[fm][fn][1] };
            float2 v1 = { acc[fm][fn][2], acc[fm][fn][3] };
            *(float2*)&C[(size_t)r0 * HID + c0]       = v0;
            *(float2*)&C[(size_t)(r0 + 8) * HID + c0] = v1;
        }
    }
}

__global__ void __launch_bounds__(256, 2) tc_qkv() {
    const size_t woff = (size_t)blockIdx.z * HID * HID;
    float* C = (blockIdx.z == 0) ? g_q : (blockIdx.z == 1) ? g_k : g_v;
    gemm_tc(g_xh, g_wh + woff, C);
}

__global__ void __launch_bounds__(256, 2) tc_o(float* __restrict__ out) {
    gemm_tc(g_ah, g_wh + (size_t)3 * HID * HID, out);
}

// ---------------- fp32 -> fp16 conversion ------------------------------------
__global__ void __launch_bounds__(256) conv_x(const float* __restrict__ x) {
    const size_t i = (size_t)blockIdx.x * 256 + threadIdx.x;
    const float4 v = ((const float4*)x)[i];
    __half2 p0 = __floats2half2_rn(v.x, v.y);
    __half2 p1 = __floats2half2_rn(v.z, v.w);
    uint2 pk = { *(uint32_t*)&p0, *(uint32_t*)&p1 };
    *(uint2*)(g_xh + i * 4) = pk;
}

__global__ void __launch_bounds__(256) conv_w(const float* __restrict__ wq,
                                              const float* __restrict__ wk,
                                              const float* __restrict__ wv,
                                              const float* __restrict__ wo) {
    const float* w = (blockIdx.y == 0) ? wq : (blockIdx.y == 1) ? wk
                   : (blockIdx.y == 2) ? wv : wo;
    const size_t i = (size_t)blockIdx.x * 256 + threadIdx.x;
    const float4 v = ((const float4*)w)[i];
    __half2 p0 = __floats2half2_rn(v.x, v.y);
    __half2 p1 = __floats2half2_rn(v.z, v.w);
    uint2 pk = { *(uint32_t*)&p0, *(uint32_t*)&p1 };
    *(uint2*)(g_wh + (size_t)blockIdx.y * HID * HID + i * 4) = pk;
}

// ---------------- per-token attention over heads (fp32, vectorized LDS) -------
__global__ void __launch_bounds__(256) attn_kernel() {
    __shared__ float sq[16][68];   // 68-pad: float4 pattern conflict-free
    __shared__ float sk[16][68];
    __shared__ float sv[16][68];
    __shared__ float sp[16][17];

    const int t   = blockIdx.x;
    const int tid = threadIdx.x;
    const size_t base = (size_t)t * HID;

    {
        const int row = tid >> 4;
        const int col = (tid & 15) * 4;
        *(float4*)&sq[row][col] = *(const float4*)&g_q[base + row * HDIM + col];
        *(float4*)&sk[row][col] = *(const float4*)&g_k[base + row * HDIM + col];
        *(float4*)&sv[row][col] = *(const float4*)&g_v[base + row * HDIM + col];
    }
    __syncthreads();

    const int h = tid >> 4;
    const int g = tid & 15;

    // q[h] . k[g], explicit float4 smem reads
    const float4* q4 = (const float4*)&sq[h][0];
    const float4* k4 = (const float4*)&sk[g][0];
    float s = 0.f;
#pragma unroll
    for (int i = 0; i < 16; ++i) {
        const float4 a = q4[i];
        const float4 b = k4[i];
        s = fmaf(a.x, b.x, fmaf(a.y, b.y, fmaf(a.z, b.z, fmaf(a.w, b.w, s))));
    }
    s *= 0.125f;

    float m = s;
#pragma unroll
    for (int off = 8; off; off >>= 1)
        m = fmaxf(m, __shfl_xor_sync(0xffffffffu, m, off, 16));
    const float e = __expf(s - m);
    float sum = e;
#pragma unroll
    for (int off = 8; off; off >>= 1)
        sum += __shfl_xor_sync(0xffffffffu, sum, off, 16);
    sp[h][g] = e / sum;
    __syncthreads();

    const int d0 = (tid & 15) * 4;
    float4 o = { 0.f, 0.f, 0.f, 0.f };
#pragma unroll
    for (int gg = 0; gg < 16; ++gg) {
        const float p = sp[h][gg];
        const float4 v = *(const float4*)&sv[gg][d0];
        o.x = fmaf(p, v.x, o.x);
        o.y = fmaf(p, v.y, o.y);
        o.z = fmaf(p, v.z, o.z);
        o.w = fmaf(p, v.w, o.w);
    }

    // fp16 for the O-projection GEMM
    __half2 p0 = __floats2half2_rn(o.x, o.y);
    __half2 p1 = __floats2half2_rn(o.z, o.w);
    uint2 pk = { *(uint32_t*)&p0, *(uint32_t*)&p1 };
    *(uint2*)&g_ah[base + h * HDIM + d0] = pk;
}

// ---------------------------------------------------------------------------
extern "C" void kernel_launch(void* const* d_in, const int* in_sizes, int n_in,
                              void* d_out, int out_size)
{
    const float* x  = (const float*)d_in[0];
    const float* wq = (const float*)d_in[1];
    const float* wk = (const float*)d_in[2];
    const float* wv = (const float*)d_in[3];
    const float* wo = (const float*)d_in[4];
    float* out = (float*)d_out;

    cudaFuncSetAttribute(tc_qkv, cudaFuncAttributeMaxDynamicSharedMemorySize, SMEM_BYTES);
    cudaFuncSetAttribute(tc_o,   cudaFuncAttributeMaxDynamicSharedMemorySize, SMEM_BYTES);

    conv_x<<<NTOK * HID / 4 / 256, 256>>>(x);
    conv_w<<<dim3(HID * HID / 4 / 256, 4), 256>>>(wq, wk, wv, wo);

    dim3 gqkv(HID / 128, NTOK / 128, 3);
    tc_qkv<<<gqkv, 256, SMEM_BYTES>>>();

    attn_kernel<<<NTOK, 256>>>();

    dim3 go(HID / 128, NTOK / 128, 1);
    tc_o<<<go, 256, SMEM_BYTES>>>(out);
}

// round 6
// speedup vs baseline: 5.8998x; 1.0249x over previous
#include <cuda_runtime.h>
#include <cuda_fp16.h>
#include <cstdint>

#define NTOK   16384
#define HID    1024
#define HDIM   64

// ---------------- scratch (device globals; no cudaMalloc allowed) -------------
__device__ __align__(256) __half g_xh[NTOK * HID];
__device__ __align__(256) __half g_wh[4 * HID * HID];
__device__ __align__(256) __half g_q[NTOK * HID];
__device__ __align__(256) __half g_k[NTOK * HID];
__device__ __align__(256) __half g_v[NTOK * HID];
__device__ __align__(256) __half g_ah[NTOK * HID];

// ---------------- PTX helpers (plain-sm_103-legal) -----------------------------
__device__ __forceinline__ uint32_t smem_u32(const void* p) {
    uint32_t a;
    asm("{ .reg .u64 t; cvta.to.shared.u64 t, %1; cvt.u32.u64 %0, t; }" : "=r"(a) : "l"(p));
    return a;
}

__device__ __forceinline__ void cp_async16(uint32_t saddr, const void* gptr) {
    asm volatile("cp.async.cg.shared.global [%0], [%1], 16;"
                 :: "r"(saddr), "l"(__cvta_generic_to_global(gptr)) : "memory");
}
__device__ __forceinline__ void cp_commit() {
    asm volatile("cp.async.commit_group;" ::: "memory");
}
template <int N>
__device__ __forceinline__ void cp_wait() {
    asm volatile("cp.async.wait_group %0;" :: "n"(N) : "memory");
}

__device__ __forceinline__ void ldsm4(uint32_t addr, uint32_t* r) {
    asm volatile("ldmatrix.sync.aligned.m8n8.x4.shared.b16 {%0,%1,%2,%3}, [%4];"
                 : "=r"(r[0]), "=r"(r[1]), "=r"(r[2]), "=r"(r[3]) : "r"(addr));
}

// D += A * B  (m16n8k16, fp16 in, fp32 acc)
__device__ __forceinline__ void mma_fp16(float* c, const uint32_t* a, const uint32_t* b) {
    asm volatile("mma.sync.aligned.m16n8k16.row.col.f32.f16.f16.f32 "
                 "{%0,%1,%2,%3}, {%4,%5,%6,%7}, {%8,%9}, {%0,%1,%2,%3};"
                 : "+f"(c[0]), "+f"(c[1]), "+f"(c[2]), "+f"(c[3])
                 : "r"(a[0]), "r"(a[1]), "r"(a[2]), "r"(a[3]), "r"(b[0]), "r"(b[1]));
}

// ---------------- GEMM geometry ----------------------------------------------
// CTA tile 128x256, warp tile 64x64 (8 warps), BK=64, 4-slot cp.async pipeline.
// smem per slot: A 128x128B (16KB) + B 256x128B (32KB) = 48KB; 4 slots = 192KB.
#define BM         128
#define BN         256
#define BK         64
#define A_BYTES    16384
#define SLOT_BYTES 49152
#define NSLOTS     4
#define SMEM_BYTES (NSLOTS * SLOT_BYTES)
#define NSTAGES    (HID / BK)     // 16

// ldmatrix.x4 address: R = first row of 16-row group, kb = byte offset of k16 chunk
__device__ __forceinline__ uint32_t frag_addr(uint32_t base, int R, int kb, int lane) {
    const int row = R + (lane & 7) + ((lane >> 3) & 1) * 8;
    const int kc  = kb + (lane >> 4) * 16;
    const uint32_t bo = (uint32_t)(row * 128 + kc);
    return base + (bo ^ (uint32_t)((row & 7) << 4));
}

__device__ __forceinline__ void load_stage(uint32_t slot_base,
                                           const __half* __restrict__ A,
                                           const __half* __restrict__ B,
                                           int k0, int tid)
{
    // A: 128 rows x 8 chunks = 1024 chunks of 16B
#pragma unroll
    for (int j = 0; j < 4; ++j) {
        const int id  = tid + j * 256;
        const int row = id >> 3;
        const int c   = id & 7;
        const uint32_t bo = (uint32_t)(row * 128 + c * 16);
        const uint32_t sw = bo ^ (uint32_t)((row & 7) << 4);
        cp_async16(slot_base + sw, A + (size_t)row * HID + k0 + c * 8);
    }
    // B: 256 rows x 8 chunks = 2048 chunks
#pragma unroll
    for (int j = 0; j < 8; ++j) {
        const int id  = tid + j * 256;
        const int row = id >> 3;
        const int c   = id & 7;
        const uint32_t bo = (uint32_t)(row * 128 + c * 16);
        const uint32_t sw = bo ^ (uint32_t)((row & 7) << 4);
        cp_async16(slot_base + A_BYTES + sw, B + (size_t)row * HID + k0 + c * 8);
    }
    cp_commit();
}

// ---------------- fp16 tensor-core GEMM --------------------------------------
// C[M,1024] = A[M,1024] @ B[1024,1024]^T ; OutT = __half or float
template <typename OutT>
__device__ __forceinline__ void gemm_tc(const __half* __restrict__ A,
                                        const __half* __restrict__ B,
                                        OutT* __restrict__ C)
{
    extern __shared__ char smem[];
    const uint32_t sbase = smem_u32(smem);
    const int tid  = threadIdx.x;
    const int wid  = tid >> 5;
    const int lane = tid & 31;
    const int bm   = blockIdx.y * BM;
    const int bn   = blockIdx.x * BN;
    const int wm   = (wid >> 2) * 64;   // 0 or 64
    const int wn   = (wid & 3) * 64;    // 0,64,128,192

    const __half* Ab = A + (size_t)bm * HID;
    const __half* Bb = B + (size_t)bn * HID;

    float acc[4][8][4];
#pragma unroll
    for (int i = 0; i < 4; ++i)
#pragma unroll
        for (int j = 0; j < 8; ++j)
#pragma unroll
            for (int r = 0; r < 4; ++r) acc[i][j][r] = 0.f;

    load_stage(sbase,                  Ab, Bb, 0 * BK, tid);
    load_stage(sbase + 1 * SLOT_BYTES, Ab, Bb, 1 * BK, tid);
    load_stage(sbase + 2 * SLOT_BYTES, Ab, Bb, 2 * BK, tid);

#pragma unroll 1
    for (int t = 0; t < NSTAGES; ++t) {
        if (t <= NSTAGES - 3)      cp_wait<2>();
        else if (t == NSTAGES - 2) cp_wait<1>();
        else                       cp_wait<0>();
        __syncthreads();

        if (t + 3 < NSTAGES) {
            const int slot = (t + 3) % NSLOTS;
            load_stage(sbase + slot * SLOT_BYTES, Ab, Bb, (t + 3) * BK, tid);
        }

        const uint32_t sA = sbase + (t % NSLOTS) * SLOT_BYTES;
        const uint32_t sB = sA + A_BYTES;

#pragma unroll
        for (int s = 0; s < BK / 16; ++s) {
            const int kb = s * 32;
            uint32_t b[8][2];
#pragma unroll
            for (int p = 0; p < 4; ++p) {
                uint32_t r[4];
                ldsm4(frag_addr(sB, wn + p * 16, kb, lane), r);
                b[2 * p][0] = r[0]; b[2 * p + 1][0] = r[1];
                b[2 * p][1] = r[2]; b[2 * p + 1][1] = r[3];
            }
#pragma unroll
            for (int fm = 0; fm < 4; ++fm) {
                uint32_t a[4];
                ldsm4(frag_addr(sA, wm + fm * 16, kb, lane), a);
#pragma unroll
                for (int fn = 0; fn < 8; ++fn)
                    mma_fp16(acc[fm][fn], a, b[fn]);
            }
        }
    }

    // epilogue: register fragments -> gmem
#pragma unroll
    for (int fm = 0; fm < 4; ++fm) {
        const int r0 = bm + wm + fm * 16 + (lane >> 2);
#pragma unroll
        for (int fn = 0; fn < 8; ++fn) {
            const int c0 = bn + wn + fn * 8 + (lane & 3) * 2;
            if constexpr (sizeof(OutT) == 2) {
                __half2 h0 = __floats2half2_rn(acc[fm][fn][0], acc[fm][fn][1]);
                __half2 h1 = __floats2half2_rn(acc[fm][fn][2], acc[fm][fn][3]);
                *(__half2*)&C[(size_t)r0 * HID + c0]       = h0;
                *(__half2*)&C[(size_t)(r0 + 8) * HID + c0] = h1;
            } else {
                float2 v0 = { acc[fm][fn][0], acc[fm][fn][1] };
                float2 v1 = { acc[fm][fn][2], acc[fm][fn][3] };
                *(float2*)&C[(size_t)r0 * HID + c0]       = v0;
                *(float2*)&C[(size_t)(r0 + 8) * HID + c0] = v1;
            }
        }
    }
}

__global__ void __launch_bounds__(256, 1) tc_qkv() {
    const size_t woff = (size_t)blockIdx.z * HID * HID;
    __half* C = (blockIdx.z == 0) ? g_q : (blockIdx.z == 1) ? g_k : g_v;
    gemm_tc<__half>(g_xh, g_wh + woff, C);
}

__global__ void __launch_bounds__(256, 1) tc_o(float* __restrict__ out) {
    gemm_tc<float>(g_ah, g_wh + (size_t)3 * HID * HID, out);
}

// ---------------- fp32 -> fp16 conversion ------------------------------------
__global__ void __launch_bounds__(256) conv_x(const float* __restrict__ x) {
    const size_t i = (size_t)blockIdx.x * 256 + threadIdx.x;
    const float4 v = ((const float4*)x)[i];
    __half2 p0 = __floats2half2_rn(v.x, v.y);
    __half2 p1 = __floats2half2_rn(v.z, v.w);
    uint2 pk = { *(uint32_t*)&p0, *(uint32_t*)&p1 };
    *(uint2*)(g_xh + i * 4) = pk;
}

__global__ void __launch_bounds__(256) conv_w(const float* __restrict__ wq,
                                              const float* __restrict__ wk,
                                              const float* __restrict__ wv,
                                              const float* __restrict__ wo) {
    const float* w = (blockIdx.y == 0) ? wq : (blockIdx.y == 1) ? wk
                   : (blockIdx.y == 2) ? wv : wo;
    const size_t i = (size_t)blockIdx.x * 256 + threadIdx.x;
    const float4 v = ((const float4*)w)[i];
    __half2 p0 = __floats2half2_rn(v.x, v.y);
    __half2 p1 = __floats2half2_rn(v.z, v.w);
    uint2 pk = { *(uint32_t*)&p0, *(uint32_t*)&p1 };
    *(uint2*)(g_wh + (size_t)blockIdx.y * HID * HID + i * 4) = pk;
}

// ---------------- per-token attention over heads (fp16 I/O, fp32 math) --------
__global__ void __launch_bounds__(256) attn_kernel() {
    __shared__ __half sq[16][72];   // 144B rows: 16B-aligned for uint4 LDS
    __shared__ __half sk[16][72];
    __shared__ __half sv[16][72];
    __shared__ float  sp[16][17];

    const int t   = blockIdx.x;
    const int tid = threadIdx.x;
    const size_t base = (size_t)t * HID;

    {
        const int row = tid >> 4;            // head 0..15
        const int col = (tid & 15) * 4;      // 4 halfs per thread
        *(uint2*)&sq[row][col] = *(const uint2*)&g_q[base + row * HDIM + col];
        *(uint2*)&sk[row][col] = *(const uint2*)&g_k[base + row * HDIM + col];
        *(uint2*)&sv[row][col] = *(const uint2*)&g_v[base + row * HDIM + col];
    }
    __syncthreads();

    const int h = tid >> 4;
    const int g = tid & 15;

    // q[h] . k[g]: 8 x uint4 (8 halfs each) per row
    float s = 0.f;
#pragma unroll
    for (int i = 0; i < 8; ++i) {
        const uint4 qa = *(const uint4*)&sq[h][i * 8];
        const uint4 kb = *(const uint4*)&sk[g][i * 8];
        const __half2* qh = (const __half2*)&qa;
        const __half2* kh = (const __half2*)&kb;
#pragma unroll
        for (int j = 0; j < 4; ++j) {
            const float2 a = __half22float2(qh[j]);
            const float2 b = __half22float2(kh[j]);
            s = fmaf(a.x, b.x, fmaf(a.y, b.y, s));
        }
    }
    s *= 0.125f;

    float m = s;
#pragma unroll
    for (int off = 8; off; off >>= 1)
        m = fmaxf(m, __shfl_xor_sync(0xffffffffu, m, off, 16));
    const float e = __expf(s - m);
    float sum = e;
#pragma unroll
    for (int off = 8; off; off >>= 1)
        sum += __shfl_xor_sync(0xffffffffu, sum, off, 16);
    sp[h][g] = e / sum;
    __syncthreads();

    // out[h][d0..d0+3] = sum_g p * v[g][d0..d0+3]
    const int d0 = (tid & 15) * 4;
    float4 o = { 0.f, 0.f, 0.f, 0.f };
#pragma unroll
    for (int gg = 0; gg < 16; ++gg) {
        const float p = sp[h][gg];
        const uint2 vv = *(const uint2*)&sv[gg][d0];
        const __half2* vh = (const __half2*)&vv;
        const float2 v0 = __half22float2(vh[0]);
        const float2 v1 = __half22float2(vh[1]);
        o.x = fmaf(p, v0.x, o.x);
        o.y = fmaf(p, v0.y, o.y);
        o.z = fmaf(p, v1.x, o.z);
        o.w = fmaf(p, v1.y, o.w);
    }

    __half2 p0 = __floats2half2_rn(o.x, o.y);
    __half2 p1 = __floats2half2_rn(o.z, o.w);
    uint2 pk = { *(uint32_t*)&p0, *(uint32_t*)&p1 };
    *(uint2*)&g_ah[base + h * HDIM + d0] = pk;
}

// ---------------------------------------------------------------------------
extern "C" void kernel_launch(void* const* d_in, const int* in_sizes, int n_in,
                              void* d_out, int out_size)
{
    const float* x  = (const float*)d_in[0];
    const float* wq = (const float*)d_in[1];
    const float* wk = (const float*)d_in[2];
    const float* wv = (const float*)d_in[3];
    const float* wo = (const float*)d_in[4];
    float* out = (float*)d_out;

    cudaFuncSetAttribute(tc_qkv, cudaFuncAttributeMaxDynamicSharedMemorySize, SMEM_BYTES);
    cudaFuncSetAttribute(tc_o,   cudaFuncAttributeMaxDynamicSharedMemorySize, SMEM_BYTES);

    conv_x<<<NTOK * HID / 4 / 256, 256>>>(x);
    conv_w<<<dim3(HID * HID / 4 / 256, 4), 256>>>(wq, wk, wv, wo);

    dim3 gqkv(HID / BN, NTOK / BM, 3);     // (4, 128, 3)
    tc_qkv<<<gqkv, 256, SMEM_BYTES>>>();

    attn_kernel<<<NTOK, 256>>>();

    dim3 go(HID / BN, NTOK / BM, 1);       // (4, 128, 1)
    tc_o<<<go, 256, SMEM_BYTES>>>(out);
}

// round 8
// speedup vs baseline: 6.5258x; 1.1061x over previous
#include <cuda_runtime.h>
#include <cuda_fp16.h>
#include <cstdint>

#define NTOK   16384
#define HID    1024
#define HDIM   64

// ---------------- scratch (device globals; no cudaMalloc allowed) -------------
__device__ __align__(256) __half g_xh[NTOK * HID];
__device__ __align__(256) __half g_wh[4 * HID * HID];
__device__ __align__(256) __half g_q[NTOK * HID];
__device__ __align__(256) __half g_k[NTOK * HID];
__device__ __align__(256) __half g_v[NTOK * HID];
__device__ __align__(256) __half g_ah[NTOK * HID];

// ---------------- PTX helpers (plain-sm_103-legal) -----------------------------
__device__ __forceinline__ uint32_t smem_u32(const void* p) {
    uint32_t a;
    asm("{ .reg .u64 t; cvta.to.shared.u64 t, %1; cvt.u32.u64 %0, t; }" : "=r"(a) : "l"(p));
    return a;
}

__device__ __forceinline__ void cp_async16(uint32_t saddr, const void* gptr) {
    asm volatile("cp.async.cg.shared.global [%0], [%1], 16;"
                 :: "r"(saddr), "l"(__cvta_generic_to_global(gptr)) : "memory");
}
__device__ __forceinline__ void cp_commit() {
    asm volatile("cp.async.commit_group;" ::: "memory");
}
template <int N>
__device__ __forceinline__ void cp_wait() {
    asm volatile("cp.async.wait_group %0;" :: "n"(N) : "memory");
}

__device__ __forceinline__ void ldsm4(uint32_t addr, uint32_t* r) {
    asm volatile("ldmatrix.sync.aligned.m8n8.x4.shared.b16 {%0,%1,%2,%3}, [%4];"
                 : "=r"(r[0]), "=r"(r[1]), "=r"(r[2]), "=r"(r[3]) : "r"(addr));
}

// D += A * B  (m16n8k16, fp16 in, fp32 acc)
__device__ __forceinline__ void mma_fp16(float* c, const uint32_t* a, const uint32_t* b) {
    asm volatile("mma.sync.aligned.m16n8k16.row.col.f32.f16.f16.f32 "
                 "{%0,%1,%2,%3}, {%4,%5,%6,%7}, {%8,%9}, {%0,%1,%2,%3};"
                 : "+f"(c[0]), "+f"(c[1]), "+f"(c[2]), "+f"(c[3])
                 : "r"(a[0]), "r"(a[1]), "r"(a[2]), "r"(a[3]), "r"(b[0]), "r"(b[1]));
}

// ---------------- GEMM geometry ----------------------------------------------
// CTA tile 128x128, 4 warps (2x2 of 64x64), 128 threads, BK=64.
// Slot = A 16KB + B 16KB = 32KB; 3 slots = 96KB/CTA -> 2 CTAs/SM.
#define BM         128
#define BN         128
#define BK         64
#define NTHREADS   128
#define A_BYTES    16384
#define SLOT_BYTES 32768
#define NSLOTS     3
#define SMEM_BYTES (NSLOTS * SLOT_BYTES)
#define NSTAGES    (HID / BK)     // 16

// ldmatrix.x4 address: R = first row of 16-row group, kb = byte offset of k16 chunk
__device__ __forceinline__ uint32_t frag_addr(uint32_t base, int R, int kb, int lane) {
    const int row = R + (lane & 7) + ((lane >> 3) & 1) * 8;
    const int kc  = kb + (lane >> 4) * 16;
    const uint32_t bo = (uint32_t)(row * 128 + kc);
    return base + (bo ^ (uint32_t)((row & 7) << 4));
}

__device__ __forceinline__ void load_stage(uint32_t slot_base,
                                           const __half* __restrict__ A,
                                           const __half* __restrict__ B,
                                           int k0, int tid)
{
    // A then B: each 128 rows x 8 chunks of 16B = 1024 chunks; 128 threads x 8 iters
#pragma unroll
    for (int j = 0; j < 8; ++j) {
        const int id  = tid + j * NTHREADS;
        const int row = id >> 3;
        const int c   = id & 7;
        const uint32_t bo = (uint32_t)(row * 128 + c * 16);
        const uint32_t sw = bo ^ (uint32_t)((row & 7) << 4);
        cp_async16(slot_base + sw, A + (size_t)row * HID + k0 + c * 8);
    }
#pragma unroll
    for (int j = 0; j < 8; ++j) {
        const int id  = tid + j * NTHREADS;
        const int row = id >> 3;
        const int c   = id & 7;
        const uint32_t bo = (uint32_t)(row * 128 + c * 16);
        const uint32_t sw = bo ^ (uint32_t)((row & 7) << 4);
        cp_async16(slot_base + A_BYTES + sw, B + (size_t)row * HID + k0 + c * 8);
    }
    cp_commit();
}

// ---------------- fp16 tensor-core GEMM --------------------------------------
// C[M,1024] = A[M,1024] @ B[1024,1024]^T ; OutT = __half or float
template <typename OutT>
__device__ __forceinline__ void gemm_tc(const __half* __restrict__ A,
                                        const __half* __restrict__ B,
                                        OutT* __restrict__ C)
{
    extern __shared__ char smem[];
    const uint32_t sbase = smem_u32(smem);
    const int tid  = threadIdx.x;
    const int wid  = tid >> 5;
    const int lane = tid & 31;
    const int bm   = blockIdx.y * BM;
    const int bn   = blockIdx.x * BN;
    const int wm   = (wid >> 1) * 64;   // 0 or 64
    const int wn   = (wid & 1) * 64;    // 0 or 64

    const __half* Ab = A + (size_t)bm * HID;
    const __half* Bb = B + (size_t)bn * HID;

    float acc[4][8][4];
#pragma unroll
    for (int i = 0; i < 4; ++i)
#pragma unroll
        for (int j = 0; j < 8; ++j)
#pragma unroll
            for (int r = 0; r < 4; ++r) acc[i][j][r] = 0.f;

    load_stage(sbase,                  Ab, Bb, 0 * BK, tid);
    load_stage(sbase + 1 * SLOT_BYTES, Ab, Bb, 1 * BK, tid);

#pragma unroll 1
    for (int t = 0; t < NSTAGES; ++t) {
        if (t < NSTAGES - 1) cp_wait<1>(); else cp_wait<0>();
        __syncthreads();

        if (t + 2 < NSTAGES) {
            const int slot = (t + 2) % NSLOTS;
            load_stage(sbase + slot * SLOT_BYTES, Ab, Bb, (t + 2) * BK, tid);
        }

        const uint32_t sA = sbase + (t % NSLOTS) * SLOT_BYTES;
        const uint32_t sB = sA + A_BYTES;

#pragma unroll
        for (int s = 0; s < BK / 16; ++s) {
            const int kb = s * 32;
            uint32_t b[8][2];
#pragma unroll
            for (int p = 0; p < 4; ++p) {
                uint32_t r[4];
                ldsm4(frag_addr(sB, wn + p * 16, kb, lane), r);
                b[2 * p][0] = r[0]; b[2 * p + 1][0] = r[1];
                b[2 * p][1] = r[2]; b[2 * p + 1][1] = r[3];
            }
#pragma unroll
            for (int fm = 0; fm < 4; ++fm) {
                uint32_t a[4];
                ldsm4(frag_addr(sA, wm + fm * 16, kb, lane), a);
#pragma unroll
                for (int fn = 0; fn < 8; ++fn)
                    mma_fp16(acc[fm][fn], a, b[fn]);
            }
        }
    }

    // epilogue: register fragments -> gmem
#pragma unroll
    for (int fm = 0; fm < 4; ++fm) {
        const int r0 = bm + wm + fm * 16 + (lane >> 2);
#pragma unroll
        for (int fn = 0; fn < 8; ++fn) {
            const int c0 = bn + wn + fn * 8 + (lane & 3) * 2;
            if constexpr (sizeof(OutT) == 2) {
                __half2 h0 = __floats2half2_rn(acc[fm][fn][0], acc[fm][fn][1]);
                __half2 h1 = __floats2half2_rn(acc[fm][fn][2], acc[fm][fn][3]);
                *(__half2*)&C[(size_t)r0 * HID + c0]       = h0;
                *(__half2*)&C[(size_t)(r0 + 8) * HID + c0] = h1;
            } else {
                float2 v0 = { acc[fm][fn][0], acc[fm][fn][1] };
                float2 v1 = { acc[fm][fn][2], acc[fm][fn][3] };
                *(float2*)&C[(size_t)r0 * HID + c0]       = v0;
                *(float2*)&C[(size_t)(r0 + 8) * HID + c0] = v1;
            }
        }
    }
}

__global__ void __launch_bounds__(NTHREADS, 2) tc_qkv() {
    const size_t woff = (size_t)blockIdx.z * HID * HID;
    __half* C = (blockIdx.z == 0) ? g_q : (blockIdx.z == 1) ? g_k : g_v;
    gemm_tc<__half>(g_xh, g_wh + woff, C);
}

__global__ void __launch_bounds__(NTHREADS, 2) tc_o(float* __restrict__ out) {
    gemm_tc<float>(g_ah, g_wh + (size_t)3 * HID * HID, out);
}

// ---------------- fp32 -> fp16 conversion ------------------------------------
__global__ void __launch_bounds__(256) conv_x(const float* __restrict__ x) {
    const size_t i = (size_t)blockIdx.x * 256 + threadIdx.x;
    const float4 v = ((const float4*)x)[i];
    __half2 p0 = __floats2half2_rn(v.x, v.y);
    __half2 p1 = __floats2half2_rn(v.z, v.w);
    uint2 pk = { *(uint32_t*)&p0, *(uint32_t*)&p1 };
    *(uint2*)(g_xh + i * 4) = pk;
}

__global__ void __launch_bounds__(256) conv_w(const float* __restrict__ wq,
                                              const float* __restrict__ wk,
                                              const float* __restrict__ wv,
                                              const float* __restrict__ wo) {
    const float* w = (blockIdx.y == 0) ? wq : (blockIdx.y == 1) ? wk
                   : (blockIdx.y == 2) ? wv : wo;
    const size_t i = (size_t)blockIdx.x * 256 + threadIdx.x;
    const float4 v = ((const float4*)w)[i];
    __half2 p0 = __floats2half2_rn(v.x, v.y);
    __half2 p1 = __floats2half2_rn(v.z, v.w);
    uint2 pk = { *(uint32_t*)&p0, *(uint32_t*)&p1 };
    *(uint2*)(g_wh + (size_t)blockIdx.y * HID * HID + i * 4) = pk;
}

// ---------------- per-token attention over heads (fp16 I/O, fp32 math) --------
__global__ void __launch_bounds__(256) attn_kernel() {
    __shared__ __half sq[16][72];   // 144B rows: 16B-aligned for uint4 LDS
    __shared__ __half sk[16][72];
    __shared__ __half sv[16][72];
    __shared__ float  sp[16][17];

    const int t   = blockIdx.x;
    const int tid = threadIdx.x;
    const size_t base = (size_t)t * HID;

    {
        const int row = tid >> 4;            // head 0..15
        const int col = (tid & 15) * 4;      // 4 halfs per thread
        *(uint2*)&sq[row][col] = *(const uint2*)&g_q[base + row * HDIM + col];
        *(uint2*)&sk[row][col] = *(const uint2*)&g_k[base + row * HDIM + col];
        *(uint2*)&sv[row][col] = *(const uint2*)&g_v[base + row * HDIM + col];
    }
    __syncthreads();

    const int h = tid >> 4;
    const int g = tid & 15;

    // q[h] . k[g]: 8 x uint4 (8 halfs each) per row
    float s = 0.f;
#pragma unroll
    for (int i = 0; i < 8; ++i) {
        const uint4 qa = *(const uint4*)&sq[h][i * 8];
        const uint4 kb = *(const uint4*)&sk[g][i * 8];
        const __half2* qh = (const __half2*)&qa;
        const __half2* kh = (const __half2*)&kb;
#pragma unroll
        for (int j = 0; j < 4; ++j) {
            const float2 a = __half22float2(qh[j]);
            const float2 b = __half22float2(kh[j]);
            s = fmaf(a.x, b.x, fmaf(a.y, b.y, s));
        }
    }
    s *= 0.125f;

    float m = s;
#pragma unroll
    for (int off = 8; off; off >>= 1)
        m = fmaxf(m, __shfl_xor_sync(0xffffffffu, m, off, 16));
    const float e = __expf(s - m);
    float sum = e;
#pragma unroll
    for (int off = 8; off; off >>= 1)
        sum += __shfl_xor_sync(0xffffffffu, sum, off, 16);
    sp[h][g] = e / sum;
    __syncthreads();

    // out[h][d0..d0+3] = sum_g p * v[g][d0..d0+3]
    const int d0 = (tid & 15) * 4;
    float4 o = { 0.f, 0.f, 0.f, 0.f };
#pragma unroll
    for (int gg = 0; gg < 16; ++gg) {
        const float p = sp[h][gg];
        const uint2 vv = *(const uint2*)&sv[gg][d0];
        const __half2* vh = (const __half2*)&vv;
        const float2 v0 = __half22float2(vh[0]);
        const float2 v1 = __half22float2(vh[1]);
        o.x = fmaf(p, v0.x, o.x);
        o.y = fmaf(p, v0.y, o.y);
        o.z = fmaf(p, v1.x, o.z);
        o.w = fmaf(p, v1.y, o.w);
    }

    __half2 p0 = __floats2half2_rn(o.x, o.y);
    __half2 p1 = __floats2half2_rn(o.z, o.w);
    uint2 pk = { *(uint32_t*)&p0, *(uint32_t*)&p1 };
    *(uint2*)&g_ah[base + h * HDIM + d0] = pk;
}

// ---------------------------------------------------------------------------
extern "C" void kernel_launch(void* const* d_in, const int* in_sizes, int n_in,
                              void* d_out, int out_size)
{
    const float* x  = (const float*)d_in[0];
    const float* wq = (const float*)d_in[1];
    const float* wk = (const float*)d_in[2];
    const float* wv = (const float*)d_in[3];
    const float* wo = (const float*)d_in[4];
    float* out = (float*)d_out;

    cudaFuncSetAttribute(tc_qkv, cudaFuncAttributeMaxDynamicSharedMemorySize, SMEM_BYTES);
    cudaFuncSetAttribute(tc_o,   cudaFuncAttributeMaxDynamicSharedMemorySize, SMEM_BYTES);

    conv_x<<<NTOK * HID / 4 / 256, 256>>>(x);
    conv_w<<<dim3(HID * HID / 4 / 256, 4), 256>>>(wq, wk, wv, wo);

    dim3 gqkv(HID / BN, NTOK / BM, 3);     // (8, 128, 3)
    tc_qkv<<<gqkv, NTHREADS, SMEM_BYTES>>>();

    attn_kernel<<<NTOK, 256>>>();

    dim3 go(HID / BN, NTOK / BM, 1);       // (8, 128, 1)
    tc_o<<<go, NTHREADS, SMEM_BYTES>>>(out);
}

// round 10
// speedup vs baseline: 7.2217x; 1.1066x over previous
#include <cuda_runtime.h>
#include <cuda_fp16.h>
#include <cstdint>

#define NTOK   16384
#define HID    1024
#define HDIM   64

// ---------------- scratch (device globals; no cudaMalloc allowed) -------------
__device__ __align__(256) __half g_xh[NTOK * HID];
__device__ __align__(256) __half g_wh[4 * HID * HID];
__device__ __align__(256) __half g_q[NTOK * HID];
__device__ __align__(256) __half g_k[NTOK * HID];
__device__ __align__(256) __half g_v[NTOK * HID];
__device__ __align__(256) __half g_ah[NTOK * HID];

// ---------------- PTX helpers (plain-sm_103-legal) -----------------------------
__device__ __forceinline__ uint32_t smem_u32(const void* p) {
    uint32_t a;
    asm("{ .reg .u64 t; cvta.to.shared.u64 t, %1; cvt.u32.u64 %0, t; }" : "=r"(a) : "l"(p));
    return a;
}

__device__ __forceinline__ void cp_async16(uint32_t saddr, const void* gptr) {
    asm volatile("cp.async.cg.shared.global [%0], [%1], 16;"
                 :: "r"(saddr), "l"(__cvta_generic_to_global(gptr)) : "memory");
}
__device__ __forceinline__ void cp_commit() {
    asm volatile("cp.async.commit_group;" ::: "memory");
}
template <int N>
__device__ __forceinline__ void cp_wait() {
    asm volatile("cp.async.wait_group %0;" :: "n"(N) : "memory");
}

__device__ __forceinline__ void ldsm4(uint32_t addr, uint32_t* r) {
    asm volatile("ldmatrix.sync.aligned.m8n8.x4.shared.b16 {%0,%1,%2,%3}, [%4];"
                 : "=r"(r[0]), "=r"(r[1]), "=r"(r[2]), "=r"(r[3]) : "r"(addr));
}
__device__ __forceinline__ void ldsm4t(uint32_t addr, uint32_t* r) {
    asm volatile("ldmatrix.sync.aligned.m8n8.x4.trans.shared.b16 {%0,%1,%2,%3}, [%4];"
                 : "=r"(r[0]), "=r"(r[1]), "=r"(r[2]), "=r"(r[3]) : "r"(addr));
}

// D += A * B  (m16n8k16, fp16 in, fp32 acc)
__device__ __forceinline__ void mma_fp16(float* c, const uint32_t* a, const uint32_t* b) {
    asm volatile("mma.sync.aligned.m16n8k16.row.col.f32.f16.f16.f32 "
                 "{%0,%1,%2,%3}, {%4,%5,%6,%7}, {%8,%9}, {%0,%1,%2,%3};"
                 : "+f"(c[0]), "+f"(c[1]), "+f"(c[2]), "+f"(c[3])
                 : "r"(a[0]), "r"(a[1]), "r"(a[2]), "r"(a[3]), "r"(b[0]), "r"(b[1]));
}

// ---------------- GEMM geometry ----------------------------------------------
// CTA tile 128x128, 4 warps (2x2 of 64x64), 128 threads, BK=64.
// Slot = A 16KB + B 16KB = 32KB; 3 slots = 96KB/CTA -> 2 CTAs/SM.
#define BM         128
#define BN         128
#define BK         64
#define NTHREADS   128
#define A_BYTES    16384
#define SLOT_BYTES 32768
#define NSLOTS     3
#define SMEM_BYTES (NSLOTS * SLOT_BYTES)
#define NSTAGES    (HID / BK)     // 16

// ldmatrix.x4 address: R = first row of 16-row group, kb = byte offset of k16 chunk
__device__ __forceinline__ uint32_t frag_addr(uint32_t base, int R, int kb, int lane) {
    const int row = R + (lane & 7) + ((lane >> 3) & 1) * 8;
    const int kc  = kb + (lane >> 4) * 16;
    const uint32_t bo = (uint32_t)(row * 128 + kc);
    return base + (bo ^ (uint32_t)((row & 7) << 4));
}

__device__ __forceinline__ void load_stage(uint32_t slot_base,
                                           const __half* __restrict__ A,
                                           const __half* __restrict__ B,
                                           int k0, int tid)
{
#pragma unroll
    for (int j = 0; j < 8; ++j) {
        const int id  = tid + j * NTHREADS;
        const int row = id >> 3;
        const int c   = id & 7;
        const uint32_t bo = (uint32_t)(row * 128 + c * 16);
        const uint32_t sw = bo ^ (uint32_t)((row & 7) << 4);
        cp_async16(slot_base + sw, A + (size_t)row * HID + k0 + c * 8);
    }
#pragma unroll
    for (int j = 0; j < 8; ++j) {
        const int id  = tid + j * NTHREADS;
        const int row = id >> 3;
        const int c   = id & 7;
        const uint32_t bo = (uint32_t)(row * 128 + c * 16);
        const uint32_t sw = bo ^ (uint32_t)((row & 7) << 4);
        cp_async16(slot_base + A_BYTES + sw, B + (size_t)row * HID + k0 + c * 8);
    }
    cp_commit();
}

// ---------------- fp16 tensor-core GEMM --------------------------------------
template <typename OutT>
__device__ __forceinline__ void gemm_tc(const __half* __restrict__ A,
                                        const __half* __restrict__ B,
                                        OutT* __restrict__ C)
{
    extern __shared__ char smem[];
    const uint32_t sbase = smem_u32(smem);
    const int tid  = threadIdx.x;
    const int wid  = tid >> 5;
    const int lane = tid & 31;
    const int bm   = blockIdx.y * BM;
    const int bn   = blockIdx.x * BN;
    const int wm   = (wid >> 1) * 64;   // 0 or 64
    const int wn   = (wid & 1) * 64;    // 0 or 64

    const __half* Ab = A + (size_t)bm * HID;
    const __half* Bb = B + (size_t)bn * HID;

    float acc[4][8][4];
#pragma unroll
    for (int i = 0; i < 4; ++i)
#pragma unroll
        for (int j = 0; j < 8; ++j)
#pragma unroll
            for (int r = 0; r < 4; ++r) acc[i][j][r] = 0.f;

    load_stage(sbase,                  Ab, Bb, 0 * BK, tid);
    load_stage(sbase + 1 * SLOT_BYTES, Ab, Bb, 1 * BK, tid);

#pragma unroll 1
    for (int t = 0; t < NSTAGES; ++t) {
        if (t < NSTAGES - 1) cp_wait<1>(); else cp_wait<0>();
        __syncthreads();

        if (t + 2 < NSTAGES) {
            const int slot = (t + 2) % NSLOTS;
            load_stage(sbase + slot * SLOT_BYTES, Ab, Bb, (t + 2) * BK, tid);
        }

        const uint32_t sA = sbase + (t % NSLOTS) * SLOT_BYTES;
        const uint32_t sB = sA + A_BYTES;

#pragma unroll
        for (int s = 0; s < BK / 16; ++s) {
            const int kb = s * 32;
            uint32_t b[8][2];
#pragma unroll
            for (int p = 0; p < 4; ++p) {
                uint32_t r[4];
                ldsm4(frag_addr(sB, wn + p * 16, kb, lane), r);
                b[2 * p][0] = r[0]; b[2 * p + 1][0] = r[1];
                b[2 * p][1] = r[2]; b[2 * p + 1][1] = r[3];
            }
#pragma unroll
            for (int fm = 0; fm < 4; ++fm) {
                uint32_t a[4];
                ldsm4(frag_addr(sA, wm + fm * 16, kb, lane), a);
#pragma unroll
                for (int fn = 0; fn < 8; ++fn)
                    mma_fp16(acc[fm][fn], a, b[fn]);
            }
        }
    }

#pragma unroll
    for (int fm = 0; fm < 4; ++fm) {
        const int r0 = bm + wm + fm * 16 + (lane >> 2);
#pragma unroll
        for (int fn = 0; fn < 8; ++fn) {
            const int c0 = bn + wn + fn * 8 + (lane & 3) * 2;
            if constexpr (sizeof(OutT) == 2) {
                __half2 h0 = __floats2half2_rn(acc[fm][fn][0], acc[fm][fn][1]);
                __half2 h1 = __floats2half2_rn(acc[fm][fn][2], acc[fm][fn][3]);
                *(__half2*)&C[(size_t)r0 * HID + c0]       = h0;
                *(__half2*)&C[(size_t)(r0 + 8) * HID + c0] = h1;
            } else {
                float2 v0 = { acc[fm][fn][0], acc[fm][fn][1] };
                float2 v1 = { acc[fm][fn][2], acc[fm][fn][3] };
                *(float2*)&C[(size_t)r0 * HID + c0]       = v0;
                *(float2*)&C[(size_t)(r0 + 8) * HID + c0] = v1;
            }
        }
    }
}

__global__ void __launch_bounds__(NTHREADS, 2) tc_qkv() {
    const size_t woff = (size_t)blockIdx.z * HID * HID;
    __half* C = (blockIdx.z == 0) ? g_q : (blockIdx.z == 1) ? g_k : g_v;
    gemm_tc<__half>(g_xh, g_wh + woff, C);
}

__global__ void __launch_bounds__(NTHREADS, 2) tc_o(float* __restrict__ out) {
    gemm_tc<float>(g_ah, g_wh + (size_t)3 * HID * HID, out);
}

// ---------------- fp32 -> fp16 conversion ------------------------------------
__global__ void __launch_bounds__(256) conv_x(const float* __restrict__ x) {
    const size_t i = (size_t)blockIdx.x * 256 + threadIdx.x;
    const float4 v = ((const float4*)x)[i];
    __half2 p0 = __floats2half2_rn(v.x, v.y);
    __half2 p1 = __floats2half2_rn(v.z, v.w);
    uint2 pk = { *(uint32_t*)&p0, *(uint32_t*)&p1 };
    *(uint2*)(g_xh + i * 4) = pk;
}

__global__ void __launch_bounds__(256) conv_w(const float* __restrict__ wq,
                                              const float* __restrict__ wk,
                                              const float* __restrict__ wv,
                                              const float* __restrict__ wo) {
    const float* w = (blockIdx.y == 0) ? wq : (blockIdx.y == 1) ? wk
                   : (blockIdx.y == 2) ? wv : wo;
    const size_t i = (size_t)blockIdx.x * 256 + threadIdx.x;
    const float4 v = ((const float4*)w)[i];
    __half2 p0 = __floats2half2_rn(v.x, v.y);
    __half2 p1 = __floats2half2_rn(v.z, v.w);
    uint2 pk = { *(uint32_t*)&p0, *(uint32_t*)&p1 };
    *(uint2*)(g_wh + (size_t)blockIdx.y * HID * HID + i * 4) = pk;
}

// ---------------- tensor-core per-token attention -----------------------------
// 1 warp = 1 token; 8 tokens per 256-thread block.
// S = Q(16x64) K^T -> softmax rows -> O = P(16x16) V(16x64), all via m16n8k16.
__global__ void __launch_bounds__(256) attn_kernel() {
    __shared__ __align__(128) char sm[8 * 3 * 2048];   // per token: q,k,v tiles (16x128B, swizzled)
    const uint32_t sbase = smem_u32(sm);
    const int tid  = threadIdx.x;
    const int lane = tid & 31;
    const int wid  = tid >> 5;
    const size_t tok0 = (size_t)blockIdx.x * 8;

    // cooperative load of 8 tokens' q,k,v: 3072 chunks of 16B
#pragma unroll
    for (int j = 0; j < 12; ++j) {
        const int id   = tid + j * 256;       // 0..3071
        const int w    = id / 384;            // token slot
        const int rem  = id - w * 384;
        const int tile = rem >> 7;            // 0=q 1=k 2=v
        const int c    = rem & 127;
        const int row  = c >> 3;
        const int c8   = c & 7;
        const __half* src = (tile == 0 ? g_q : tile == 1 ? g_k : g_v)
                          + (tok0 + w) * HID + row * HDIM + c8 * 8;
        const uint32_t bo = (uint32_t)(row * 128 + c8 * 16);
        const uint32_t sw = bo ^ (uint32_t)((row & 7) << 4);
        cp_async16(sbase + (uint32_t)(w * 3 + tile) * 2048 + sw, src);
    }
    cp_commit();
    cp_wait<0>();
    __syncthreads();

    const uint32_t qb = sbase + (uint32_t)(wid * 3 + 0) * 2048;
    const uint32_t kb = sbase + (uint32_t)(wid * 3 + 1) * 2048;
    const uint32_t vb = sbase + (uint32_t)(wid * 3 + 2) * 2048;

    // ---- scores: S = Q K^T (16x16), two n8 tiles, 4 k16 steps ----
    float sc[2][4];
#pragma unroll
    for (int i = 0; i < 2; ++i)
#pragma unroll
        for (int r = 0; r < 4; ++r) sc[i][r] = 0.f;

#pragma unroll
    for (int s = 0; s < 4; ++s) {
        uint32_t a[4], b[4];
        ldsm4(frag_addr(qb, 0, s * 32, lane), a);
        ldsm4(frag_addr(kb, 0, s * 32, lane), b);
        uint32_t b0[2] = { b[0], b[2] };
        uint32_t b1[2] = { b[1], b[3] };
        mma_fp16(sc[0], a, b0);
        mma_fp16(sc[1], a, b1);
    }

    // ---- softmax over 16 cols; row r=lane>>2 (lo) and r+8 (hi) ----
    float mlo = fmaxf(fmaxf(sc[0][0], sc[0][1]), fmaxf(sc[1][0], sc[1][1]));
    float mhi = fmaxf(fmaxf(sc[0][2], sc[0][3]), fmaxf(sc[1][2], sc[1][3]));
#pragma unroll
    for (int off = 1; off <= 2; off <<= 1) {
        mlo = fmaxf(mlo, __shfl_xor_sync(0xffffffffu, mlo, off));
        mhi = fmaxf(mhi, __shfl_xor_sync(0xffffffffu, mhi, off));
    }
    float plo[4], phi[4];
    plo[0] = __expf(0.125f * (sc[0][0] - mlo));
    plo[1] = __expf(0.125f * (sc[0][1] - mlo));
    plo[2] = __expf(0.125f * (sc[1][0] - mlo));
    plo[3] = __expf(0.125f * (sc[1][1] - mlo));
    phi[0] = __expf(0.125f * (sc[0][2] - mhi));
    phi[1] = __expf(0.125f * (sc[0][3] - mhi));
    phi[2] = __expf(0.125f * (sc[1][2] - mhi));
    phi[3] = __expf(0.125f * (sc[1][3] - mhi));
    float slo = plo[0] + plo[1] + plo[2] + plo[3];
    float shi = phi[0] + phi[1] + phi[2] + phi[3];
#pragma unroll
    for (int off = 1; off <= 2; off <<= 1) {
        slo += __shfl_xor_sync(0xffffffffu, slo, off);
        shi += __shfl_xor_sync(0xffffffffu, shi, off);
    }
    const float rlo = 1.f / slo, rhi = 1.f / shi;

    // P accumulator layout == A-fragment layout of the next mma: pack in-register.
    uint32_t pa[4];
    {
        __half2 h;
        h = __floats2half2_rn(plo[0] * rlo, plo[1] * rlo); pa[0] = *(uint32_t*)&h;
        h = __floats2half2_rn(phi[0] * rhi, phi[1] * rhi); pa[1] = *(uint32_t*)&h;
        h = __floats2half2_rn(plo[2] * rlo, plo[3] * rlo); pa[2] = *(uint32_t*)&h;
        h = __floats2half2_rn(phi[2] * rhi, phi[3] * rhi); pa[3] = *(uint32_t*)&h;
    }

    // ---- O = P V : 8 n8 blocks over d, k=16; V^T fragments via ldmatrix.trans ----
    float o[8][4];
#pragma unroll
    for (int j = 0; j < 8; ++j)
#pragma unroll
        for (int r = 0; r < 4; ++r) o[j][r] = 0.f;

#pragma unroll
    for (int j2 = 0; j2 < 4; ++j2) {
        uint32_t b[4];
        ldsm4t(frag_addr(vb, 0, j2 * 32, lane), b);
        uint32_t b0[2] = { b[0], b[1] };
        uint32_t b1[2] = { b[2], b[3] };
        mma_fp16(o[2 * j2],     pa, b0);
        mma_fp16(o[2 * j2 + 1], pa, b1);
    }

    // ---- stage to smem (stride-144 rows over the q/k region), coalesced store ----
    char* stp = sm + wid * 3 * 2048;
    {
        const int r  = lane >> 2;
        const int cb = (lane & 3) * 4;   // byte offset of col pair within 16B block
#pragma unroll
        for (int j = 0; j < 8; ++j) {
            __half2 lo2 = __floats2half2_rn(o[j][0], o[j][1]);
            __half2 hi2 = __floats2half2_rn(o[j][2], o[j][3]);
            *(__half2*)(stp + r * 144 + j * 16 + cb)       = lo2;
            *(__half2*)(stp + (r + 8) * 144 + j * 16 + cb) = hi2;
        }
    }
    __syncwarp();
    {
        __half* gdst = g_ah + (tok0 + wid) * HID;
#pragma unroll
        for (int l = 0; l < 4; ++l) {
            const int id  = lane + l * 32;    // 0..127
            const int row = id >> 3;
            const int c8  = id & 7;
            const uint4 v = *(const uint4*)(stp + row * 144 + c8 * 16);
            *(uint4*)(gdst + row * HDIM + c8 * 8) = v;
        }
    }
}

// ---------------------------------------------------------------------------
extern "C" void kernel_launch(void* const* d_in, const int* in_sizes, int n_in,
                              void* d_out, int out_size)
{
    const float* x  = (const float*)d_in[0];
    const float* wq = (const float*)d_in[1];
    const float* wk = (const float*)d_in[2];
    const float* wv = (const float*)d_in[3];
    const float* wo = (const float*)d_in[4];
    float* out = (float*)d_out;

    cudaFuncSetAttribute(tc_qkv, cudaFuncAttributeMaxDynamicSharedMemorySize, SMEM_BYTES);
    cudaFuncSetAttribute(tc_o,   cudaFuncAttributeMaxDynamicSharedMemorySize, SMEM_BYTES);

    conv_x<<<NTOK * HID / 4 / 256, 256>>>(x);
    conv_w<<<dim3(HID * HID / 4 / 256, 4), 256>>>(wq, wk, wv, wo);

    dim3 gqkv(HID / BN, NTOK / BM, 3);     // (8, 128, 3)
    tc_qkv<<<gqkv, NTHREADS, SMEM_BYTES>>>();

    attn_kernel<<<NTOK / 8, 256>>>();

    dim3 go(HID / BN, NTOK / BM, 1);       // (8, 128, 1)
    tc_o<<<go, NTHREADS, SMEM_BYTES>>>(out);
}

// round 12
// speedup vs baseline: 7.7164x; 1.0685x over previous
#include <cuda_runtime.h>
#include <cuda_fp16.h>
#include <cuda.h>
#include <cstdint>

#define NTOK   16384
#define HID    1024
#define HDIM   64

// ---------------- scratch (device globals; no cudaMalloc allowed) -------------
__device__ __align__(256) __half g_xh[NTOK * HID];
__device__ __align__(256) __half g_wh[4 * HID * HID];
__device__ __align__(256) __half g_q[NTOK * HID];
__device__ __align__(256) __half g_k[NTOK * HID];
__device__ __align__(256) __half g_v[NTOK * HID];
__device__ __align__(256) __half g_ah[NTOK * HID];

// ---------------- PTX helpers (plain-sm_103-legal) -----------------------------
__device__ __forceinline__ uint32_t smem_u32(const void* p) {
    uint32_t a;
    asm("{ .reg .u64 t; cvta.to.shared.u64 t, %1; cvt.u32.u64 %0, t; }" : "=r"(a) : "l"(p));
    return a;
}

__device__ __forceinline__ void cp_async16(uint32_t saddr, const void* gptr) {
    asm volatile("cp.async.cg.shared.global [%0], [%1], 16;"
                 :: "r"(saddr), "l"(__cvta_generic_to_global(gptr)) : "memory");
}
__device__ __forceinline__ void cp_commit() {
    asm volatile("cp.async.commit_group;" ::: "memory");
}
template <int N>
__device__ __forceinline__ void cp_wait() {
    asm volatile("cp.async.wait_group %0;" :: "n"(N) : "memory");
}

__device__ __forceinline__ void mbar_init(uint32_t mbar, uint32_t cnt) {
    asm volatile("mbarrier.init.shared.b64 [%0], %1;" :: "r"(mbar), "r"(cnt) : "memory");
}
__device__ __forceinline__ void mbar_expect_tx(uint32_t mbar, uint32_t bytes) {
    asm volatile("mbarrier.arrive.expect_tx.shared.b64 _, [%0], %1;"
                 :: "r"(mbar), "r"(bytes) : "memory");
}
__device__ __forceinline__ void mbar_wait(uint32_t mbar, uint32_t parity) {
    uint32_t done;
    asm volatile("{\n\t.reg .pred p;\n\tmbarrier.try_wait.parity.acquire.cta.shared::cta.b64 p, [%1], %2;\n\tselp.b32 %0, 1, 0, p;\n\t}"
                 : "=r"(done) : "r"(mbar), "r"(parity) : "memory");
    while (!done) {
        asm volatile("{\n\t.reg .pred p;\n\tmbarrier.try_wait.parity.acquire.cta.shared::cta.b64 p, [%1], %2, 0x989680;\n\tselp.b32 %0, 1, 0, p;\n\t}"
                     : "=r"(done) : "r"(mbar), "r"(parity) : "memory");
    }
}

__device__ __forceinline__ void tma_load_2d(uint32_t smem_addr, const CUtensorMap* tmap,
                                            int x, int y, uint32_t mbar) {
    asm volatile("cp.async.bulk.tensor.2d.shared::cta.global.tile.mbarrier::complete_tx::bytes "
                 "[%0], [%1, {%2, %3}], [%4];"
                 :: "r"(smem_addr), "l"(tmap), "r"(x), "r"(y), "r"(mbar) : "memory");
}

__device__ __forceinline__ void ldsm4(uint32_t addr, uint32_t* r) {
    asm volatile("ldmatrix.sync.aligned.m8n8.x4.shared.b16 {%0,%1,%2,%3}, [%4];"
                 : "=r"(r[0]), "=r"(r[1]), "=r"(r[2]), "=r"(r[3]) : "r"(addr));
}
__device__ __forceinline__ void ldsm4t(uint32_t addr, uint32_t* r) {
    asm volatile("ldmatrix.sync.aligned.m8n8.x4.trans.shared.b16 {%0,%1,%2,%3}, [%4];"
                 : "=r"(r[0]), "=r"(r[1]), "=r"(r[2]), "=r"(r[3]) : "r"(addr));
}

// D += A * B  (m16n8k16, fp16 in, fp32 acc)
__device__ __forceinline__ void mma_fp16(float* c, const uint32_t* a, const uint32_t* b) {
    asm volatile("mma.sync.aligned.m16n8k16.row.col.f32.f16.f16.f32 "
                 "{%0,%1,%2,%3}, {%4,%5,%6,%7}, {%8,%9}, {%0,%1,%2,%3};"
                 : "+f"(c[0]), "+f"(c[1]), "+f"(c[2]), "+f"(c[3])
                 : "r"(a[0]), "r"(a[1]), "r"(a[2]), "r"(a[3]), "r"(b[0]), "r"(b[1]));
}

// ---------------- GEMM geometry ----------------------------------------------
// CTA tile 128x128, 4 warps (2x2 of 64x64), 128 threads, BK=64.
// Slot = A 16KB + B 16KB = 32KB, filled by 2 TMA loads; 3 slots; 2 CTAs/SM.
#define BM         128
#define BN         128
#define BK         64
#define NTHREADS   128
#define A_BYTES    16384
#define SLOT_BYTES 32768
#define NSLOTS     3
#define SMEM_BYTES (1024 + NSLOTS * SLOT_BYTES)
#define NSTAGES    (HID / BK)     // 16

// ldmatrix.x4 address (SW128 layout, 128B rows): R = first row, kb = k16 byte offset
__device__ __forceinline__ uint32_t frag_addr(uint32_t base, int R, int kb, int lane) {
    const int row = R + (lane & 7) + ((lane >> 3) & 1) * 8;
    const int kc  = kb + (lane >> 4) * 16;
    const uint32_t bo = (uint32_t)(row * 128 + kc);
    return base + (bo ^ (uint32_t)((row & 7) << 4));
}

// ---------------- fp16 tensor-core GEMM with TMA loads ------------------------
template <typename OutT>
__device__ __forceinline__ void gemm_tma(const CUtensorMap* tA, const CUtensorMap* tB,
                                         int a_row0, int b_row0, OutT* __restrict__ C)
{
    extern __shared__ char smem[];
    const uint32_t sbase = smem_u32(smem);
    const uint32_t mb    = sbase;            // 3 mbarriers at +0,+8,+16
    const uint32_t slots = sbase + 1024;
    const int tid  = threadIdx.x;
    const int wid  = tid >> 5;
    const int lane = tid & 31;
    const int wm   = (wid >> 1) * 64;
    const int wn   = (wid & 1) * 64;

    if (tid == 0) {
        mbar_init(mb + 0, 1);
        mbar_init(mb + 8, 1);
        mbar_init(mb + 16, 1);
    }
    __syncthreads();

    if (tid == 0) {
#pragma unroll
        for (int s = 0; s < NSLOTS; ++s) {
            const uint32_t sl = slots + s * SLOT_BYTES;
            mbar_expect_tx(mb + s * 8, SLOT_BYTES);
            tma_load_2d(sl,           tA, s * BK, a_row0, mb + s * 8);
            tma_load_2d(sl + A_BYTES, tB, s * BK, b_row0, mb + s * 8);
        }
    }

    float acc[4][8][4];
#pragma unroll
    for (int i = 0; i < 4; ++i)
#pragma unroll
        for (int j = 0; j < 8; ++j)
#pragma unroll
            for (int r = 0; r < 4; ++r) acc[i][j][r] = 0.f;

#pragma unroll 1
    for (int t = 0; t < NSTAGES; ++t) {
        const int s = t % NSLOTS;
        mbar_wait(mb + s * 8, (t / NSLOTS) & 1);

        const uint32_t sA = slots + s * SLOT_BYTES;
        const uint32_t sB = sA + A_BYTES;

#pragma unroll
        for (int ks = 0; ks < BK / 16; ++ks) {
            const int kb = ks * 32;
            uint32_t b[8][2];
#pragma unroll
            for (int p = 0; p < 4; ++p) {
                uint32_t r[4];
                ldsm4(frag_addr(sB, wn + p * 16, kb, lane), r);
                b[2 * p][0] = r[0]; b[2 * p + 1][0] = r[1];
                b[2 * p][1] = r[2]; b[2 * p + 1][1] = r[3];
            }
#pragma unroll
            for (int fm = 0; fm < 4; ++fm) {
                uint32_t a[4];
                ldsm4(frag_addr(sA, wm + fm * 16, kb, lane), a);
#pragma unroll
                for (int fn = 0; fn < 8; ++fn)
                    mma_fp16(acc[fm][fn], a, b[fn]);
            }
        }
        __syncthreads();                       // slot s now free everywhere
        if (t + NSLOTS < NSTAGES && tid == 0) {
            mbar_expect_tx(mb + s * 8, SLOT_BYTES);
            tma_load_2d(sA,           tA, (t + NSLOTS) * BK, a_row0, mb + s * 8);
            tma_load_2d(sA + A_BYTES, tB, (t + NSLOTS) * BK, b_row0, mb + s * 8);
        }
    }

    // epilogue: register fragments -> gmem
#pragma unroll
    for (int fm = 0; fm < 4; ++fm) {
        const int r0 = a_row0 + wm + fm * 16 + (lane >> 2);
        const int cb = (b_row0 % HID);   // bn within the 1024-wide output
#pragma unroll
        for (int fn = 0; fn < 8; ++fn) {
            const int c0 = cb + wn + fn * 8 + (lane & 3) * 2;
            if constexpr (sizeof(OutT) == 2) {
                __half2 h0 = __floats2half2_rn(acc[fm][fn][0], acc[fm][fn][1]);
                __half2 h1 = __floats2half2_rn(acc[fm][fn][2], acc[fm][fn][3]);
                *(__half2*)&C[(size_t)r0 * HID + c0]       = h0;
                *(__half2*)&C[(size_t)(r0 + 8) * HID + c0] = h1;
            } else {
                float2 v0 = { acc[fm][fn][0], acc[fm][fn][1] };
                float2 v1 = { acc[fm][fn][2], acc[fm][fn][3] };
                *(float2*)&C[(size_t)r0 * HID + c0]       = v0;
                *(float2*)&C[(size_t)(r0 + 8) * HID + c0] = v1;
            }
        }
    }
}

__global__ void __launch_bounds__(NTHREADS, 2)
tc_qkv(const __grid_constant__ CUtensorMap tmA, const __grid_constant__ CUtensorMap tmB) {
    __half* C = (blockIdx.z == 0) ? g_q : (blockIdx.z == 1) ? g_k : g_v;
    gemm_tma<__half>(&tmA, &tmB,
                     blockIdx.y * BM,
                     blockIdx.z * HID + blockIdx.x * BN,   // row in 4096-row W map
                     C);
}

__global__ void __launch_bounds__(NTHREADS, 2)
tc_o(const __grid_constant__ CUtensorMap tmA, const __grid_constant__ CUtensorMap tmB,
     float* __restrict__ out) {
    gemm_tma<float>(&tmA, &tmB,
                    blockIdx.y * BM,
                    3 * HID + blockIdx.x * BN,
                    out);
}

// ---------------- fp32 -> fp16 conversion ------------------------------------
__global__ void __launch_bounds__(256) conv_x(const float* __restrict__ x) {
    const size_t i = (size_t)blockIdx.x * 256 + threadIdx.x;
    const float4 v = ((const float4*)x)[i];
    __half2 p0 = __floats2half2_rn(v.x, v.y);
    __half2 p1 = __floats2half2_rn(v.z, v.w);
    uint2 pk = { *(uint32_t*)&p0, *(uint32_t*)&p1 };
    *(uint2*)(g_xh + i * 4) = pk;
}

__global__ void __launch_bounds__(256) conv_w(const float* __restrict__ wq,
                                              const float* __restrict__ wk,
                                              const float* __restrict__ wv,
                                              const float* __restrict__ wo) {
    const float* w = (blockIdx.y == 0) ? wq : (blockIdx.y == 1) ? wk
                   : (blockIdx.y == 2) ? wv : wo;
    const size_t i = (size_t)blockIdx.x * 256 + threadIdx.x;
    const float4 v = ((const float4*)w)[i];
    __half2 p0 = __floats2half2_rn(v.x, v.y);
    __half2 p1 = __floats2half2_rn(v.z, v.w);
    uint2 pk = { *(uint32_t*)&p0, *(uint32_t*)&p1 };
    *(uint2*)(g_wh + (size_t)blockIdx.y * HID * HID + i * 4) = pk;
}

// ---------------- tensor-core per-token attention (validated R9) ---------------
__global__ void __launch_bounds__(256) attn_kernel() {
    __shared__ __align__(128) char sm[8 * 3 * 2048];
    const uint32_t sbase = smem_u32(sm);
    const int tid  = threadIdx.x;
    const int lane = tid & 31;
    const int wid  = tid >> 5;
    const size_t tok0 = (size_t)blockIdx.x * 8;

#pragma unroll
    for (int j = 0; j < 12; ++j) {
        const int id   = tid + j * 256;
        const int w    = id / 384;
        const int rem  = id - w * 384;
        const int tile = rem >> 7;
        const int c    = rem & 127;
        const int row  = c >> 3;
        const int c8   = c & 7;
        const __half* src = (tile == 0 ? g_q : tile == 1 ? g_k : g_v)
                          + (tok0 + w) * HID + row * HDIM + c8 * 8;
        const uint32_t bo = (uint32_t)(row * 128 + c8 * 16);
        const uint32_t sw = bo ^ (uint32_t)((row & 7) << 4);
        cp_async16(sbase + (uint32_t)(w * 3 + tile) * 2048 + sw, src);
    }
    cp_commit();
    cp_wait<0>();
    __syncthreads();

    const uint32_t qb = sbase + (uint32_t)(wid * 3 + 0) * 2048;
    const uint32_t kb = sbase + (uint32_t)(wid * 3 + 1) * 2048;
    const uint32_t vb = sbase + (uint32_t)(wid * 3 + 2) * 2048;

    float sc[2][4];
#pragma unroll
    for (int i = 0; i < 2; ++i)
#pragma unroll
        for (int r = 0; r < 4; ++r) sc[i][r] = 0.f;

#pragma unroll
    for (int s = 0; s < 4; ++s) {
        uint32_t a[4], b[4];
        ldsm4(frag_addr(qb, 0, s * 32, lane), a);
        ldsm4(frag_addr(kb, 0, s * 32, lane), b);
        uint32_t b0[2] = { b[0], b[2] };
        uint32_t b1[2] = { b[1], b[3] };
        mma_fp16(sc[0], a, b0);
        mma_fp16(sc[1], a, b1);
    }

    float mlo = fmaxf(fmaxf(sc[0][0], sc[0][1]), fmaxf(sc[1][0], sc[1][1]));
    float mhi = fmaxf(fmaxf(sc[0][2], sc[0][3]), fmaxf(sc[1][2], sc[1][3]));
#pragma unroll
    for (int off = 1; off <= 2; off <<= 1) {
        mlo = fmaxf(mlo, __shfl_xor_sync(0xffffffffu, mlo, off));
        mhi = fmaxf(mhi, __shfl_xor_sync(0xffffffffu, mhi, off));
    }
    float plo[4], phi[4];
    plo[0] = __expf(0.125f * (sc[0][0] - mlo));
    plo[1] = __expf(0.125f * (sc[0][1] - mlo));
    plo[2] = __expf(0.125f * (sc[1][0] - mlo));
    plo[3] = __expf(0.125f * (sc[1][1] - mlo));
    phi[0] = __expf(0.125f * (sc[0][2] - mhi));
    phi[1] = __expf(0.125f * (sc[0][3] - mhi));
    phi[2] = __expf(0.125f * (sc[1][2] - mhi));
    phi[3] = __expf(0.125f * (sc[1][3] - mhi));
    float slo = plo[0] + plo[1] + plo[2] + plo[3];
    float shi = phi[0] + phi[1] + phi[2] + phi[3];
#pragma unroll
    for (int off = 1; off <= 2; off <<= 1) {
        slo += __shfl_xor_sync(0xffffffffu, slo, off);
        shi += __shfl_xor_sync(0xffffffffu, shi, off);
    }
    const float rlo = 1.f / slo, rhi = 1.f / shi;

    uint32_t pa[4];
    {
        __half2 h;
        h = __floats2half2_rn(plo[0] * rlo, plo[1] * rlo); pa[0] = *(uint32_t*)&h;
        h = __floats2half2_rn(phi[0] * rhi, phi[1] * rhi); pa[1] = *(uint32_t*)&h;
        h = __floats2half2_rn(plo[2] * rlo, plo[3] * rlo); pa[2] = *(uint32_t*)&h;
        h = __floats2half2_rn(phi[2] * rhi, phi[3] * rhi); pa[3] = *(uint32_t*)&h;
    }

    float o[8][4];
#pragma unroll
    for (int j = 0; j < 8; ++j)
#pragma unroll
        for (int r = 0; r < 4; ++r) o[j][r] = 0.f;

#pragma unroll
    for (int j2 = 0; j2 < 4; ++j2) {
        uint32_t b[4];
        ldsm4t(frag_addr(vb, 0, j2 * 32, lane), b);
        uint32_t b0[2] = { b[0], b[1] };
        uint32_t b1[2] = { b[2], b[3] };
        mma_fp16(o[2 * j2],     pa, b0);
        mma_fp16(o[2 * j2 + 1], pa, b1);
    }

    char* stp = sm + wid * 3 * 2048;
    {
        const int r  = lane >> 2;
        const int cb = (lane & 3) * 4;
#pragma unroll
        for (int j = 0; j < 8; ++j) {
            __half2 lo2 = __floats2half2_rn(o[j][0], o[j][1]);
            __half2 hi2 = __floats2half2_rn(o[j][2], o[j][3]);
            *(__half2*)(stp + r * 144 + j * 16 + cb)       = lo2;
            *(__half2*)(stp + (r + 8) * 144 + j * 16 + cb) = hi2;
        }
    }
    __syncwarp();
    {
        __half* gdst = g_ah + (tok0 + wid) * HID;
#pragma unroll
        for (int l = 0; l < 4; ++l) {
            const int id  = lane + l * 32;
            const int row = id >> 3;
            const int c8  = id & 7;
            const uint4 v = *(const uint4*)(stp + row * 144 + c8 * 16);
            *(uint4*)(gdst + row * HDIM + c8 * 8) = v;
        }
    }
}

// ---------------- host: tensor-map creation + launch ---------------------------
typedef CUresult (*PFN_encodeTiled)(CUtensorMap*, CUtensorMapDataType, cuuint32_t,
                                    void*, const cuuint64_t*, const cuuint64_t*,
                                    const cuuint32_t*, const cuuint32_t*,
                                    CUtensorMapInterleave, CUtensorMapSwizzle,
                                    CUtensorMapL2promotion, CUtensorMapFloatOOBfill);

static void make_map(PFN_encodeTiled enc, CUtensorMap* tm, void* base, uint64_t rows) {
    cuuint64_t dims[2]    = { (cuuint64_t)HID, (cuuint64_t)rows };
    cuuint64_t strides[1] = { (cuuint64_t)(HID * sizeof(__half)) };
    cuuint32_t box[2]     = { BK, BM };      // 64 fp16 = 128B (SW128 max), 128 rows
    cuuint32_t estr[2]    = { 1, 1 };
    enc(tm, CU_TENSOR_MAP_DATA_TYPE_FLOAT16, 2, base, dims, strides, box, estr,
        CU_TENSOR_MAP_INTERLEAVE_NONE, CU_TENSOR_MAP_SWIZZLE_128B,
        CU_TENSOR_MAP_L2_PROMOTION_L2_128B, CU_TENSOR_MAP_FLOAT_OOB_FILL_NONE);
}

extern "C" void kernel_launch(void* const* d_in, const int* in_sizes, int n_in,
                              void* d_out, int out_size)
{
    const float* x  = (const float*)d_in[0];
    const float* wq = (const float*)d_in[1];
    const float* wk = (const float*)d_in[2];
    const float* wv = (const float*)d_in[3];
    const float* wo = (const float*)d_in[4];
    float* out = (float*)d_out;

    void* fn = nullptr;
#if CUDART_VERSION >= 12050
    cudaDriverEntryPointQueryResult qr;
    cudaGetDriverEntryPointByVersion("cuTensorMapEncodeTiled", &fn, 12000,
                                     cudaEnableDefault, &qr);
#else
    cudaGetDriverEntryPoint("cuTensorMapEncodeTiled", &fn, cudaEnableDefault, nullptr);
#endif
    PFN_encodeTiled enc = (PFN_encodeTiled)fn;

    void *pxh, *pwh, *pah;
    cudaGetSymbolAddress(&pxh, g_xh);
    cudaGetSymbolAddress(&pwh, g_wh);
    cudaGetSymbolAddress(&pah, g_ah);

    alignas(64) CUtensorMap tmX, tmW, tmA;
    make_map(enc, &tmX, pxh, NTOK);
    make_map(enc, &tmW, pwh, 4 * HID);
    make_map(enc, &tmA, pah, NTOK);

    cudaFuncSetAttribute(tc_qkv, cudaFuncAttributeMaxDynamicSharedMemorySize, SMEM_BYTES);
    cudaFuncSetAttribute(tc_o,   cudaFuncAttributeMaxDynamicSharedMemorySize, SMEM_BYTES);

    conv_x<<<NTOK * HID / 4 / 256, 256>>>(x);
    conv_w<<<dim3(HID * HID / 4 / 256, 4), 256>>>(wq, wk, wv, wo);

    dim3 gqkv(HID / BN, NTOK / BM, 3);     // (8, 128, 3)
    tc_qkv<<<gqkv, NTHREADS, SMEM_BYTES>>>(tmX, tmW);

    attn_kernel<<<NTOK / 8, 256>>>();

    dim3 go(HID / BN, NTOK / BM, 1);       // (8, 128, 1)
    tc_o<<<go, NTHREADS, SMEM_BYTES>>>(tmA, tmW, out);
}

// round 14
// speedup vs baseline: 7.7992x; 1.0107x over previous
#include <cuda_runtime.h>
#include <cuda_fp16.h>
#include <cuda.h>
#include <cstdint>

#define NTOK   16384
#define HID    1024
#define HDIM   64

// ---------------- scratch (device globals; no cudaMalloc allowed) -------------
__device__ __align__(256) __half g_xh[NTOK * HID];
__device__ __align__(256) __half g_wh[4 * HID * HID];
__device__ __align__(256) __half g_q[NTOK * HID];
__device__ __align__(256) __half g_k[NTOK * HID];
__device__ __align__(256) __half g_v[NTOK * HID];
__device__ __align__(256) __half g_ah[NTOK * HID];

// ---------------- PTX helpers (plain-sm_103-legal) -----------------------------
__device__ __forceinline__ uint32_t smem_u32(const void* p) {
    uint32_t a;
    asm("{ .reg .u64 t; cvta.to.shared.u64 t, %1; cvt.u32.u64 %0, t; }" : "=r"(a) : "l"(p));
    return a;
}

__device__ __forceinline__ void cp_async16(uint32_t saddr, const void* gptr) {
    asm volatile("cp.async.cg.shared.global [%0], [%1], 16;"
                 :: "r"(saddr), "l"(__cvta_generic_to_global(gptr)) : "memory");
}
__device__ __forceinline__ void cp_commit() {
    asm volatile("cp.async.commit_group;" ::: "memory");
}
template <int N>
__device__ __forceinline__ void cp_wait() {
    asm volatile("cp.async.wait_group %0;" :: "n"(N) : "memory");
}

__device__ __forceinline__ void mbar_init(uint32_t mbar, uint32_t cnt) {
    asm volatile("mbarrier.init.shared.b64 [%0], %1;" :: "r"(mbar), "r"(cnt) : "memory");
}
__device__ __forceinline__ void mbar_expect_tx(uint32_t mbar, uint32_t bytes) {
    asm volatile("mbarrier.arrive.expect_tx.shared.b64 _, [%0], %1;"
                 :: "r"(mbar), "r"(bytes) : "memory");
}
__device__ __forceinline__ void mbar_wait(uint32_t mbar, uint32_t parity) {
    uint32_t done;
    asm volatile("{\n\t.reg .pred p;\n\tmbarrier.try_wait.parity.acquire.cta.shared::cta.b64 p, [%1], %2;\n\tselp.b32 %0, 1, 0, p;\n\t}"
                 : "=r"(done) : "r"(mbar), "r"(parity) : "memory");
    while (!done) {
        asm volatile("{\n\t.reg .pred p;\n\tmbarrier.try_wait.parity.acquire.cta.shared::cta.b64 p, [%1], %2, 0x989680;\n\tselp.b32 %0, 1, 0, p;\n\t}"
                     : "=r"(done) : "r"(mbar), "r"(parity) : "memory");
    }
}

__device__ __forceinline__ void tma_load_2d(uint32_t smem_addr, const CUtensorMap* tmap,
                                            int x, int y, uint32_t mbar) {
    asm volatile("cp.async.bulk.tensor.2d.shared::cta.global.tile.mbarrier::complete_tx::bytes "
                 "[%0], [%1, {%2, %3}], [%4];"
                 :: "r"(smem_addr), "l"(tmap), "r"(x), "r"(y), "r"(mbar) : "memory");
}

__device__ __forceinline__ void ldsm4(uint32_t addr, uint32_t* r) {
    asm volatile("ldmatrix.sync.aligned.m8n8.x4.shared.b16 {%0,%1,%2,%3}, [%4];"
                 : "=r"(r[0]), "=r"(r[1]), "=r"(r[2]), "=r"(r[3]) : "r"(addr));
}
__device__ __forceinline__ void ldsm4t(uint32_t addr, uint32_t* r) {
    asm volatile("ldmatrix.sync.aligned.m8n8.x4.trans.shared.b16 {%0,%1,%2,%3}, [%4];"
                 : "=r"(r[0]), "=r"(r[1]), "=r"(r[2]), "=r"(r[3]) : "r"(addr));
}

// D += A * B  (m16n8k16, fp16 in, fp32 acc)
__device__ __forceinline__ void mma_fp16(float* c, const uint32_t* a, const uint32_t* b) {
    asm volatile("mma.sync.aligned.m16n8k16.row.col.f32.f16.f16.f32 "
                 "{%0,%1,%2,%3}, {%4,%5,%6,%7}, {%8,%9}, {%0,%1,%2,%3};"
                 : "+f"(c[0]), "+f"(c[1]), "+f"(c[2]), "+f"(c[3])
                 : "r"(a[0]), "r"(a[1]), "r"(a[2]), "r"(a[3]), "r"(b[0]), "r"(b[1]));
}

// ---------------- GEMM geometry (EXACT R12 known-good config) ------------------
// CTA tile 128x128, 4 warps (2x2 of 64x64), 128 threads, BK=64.
// Slot = A 16KB + B 16KB = 32KB via 2 TMA loads; 3 slots; 2 CTAs/SM.
#define BM         128
#define BN         128
#define BK         64
#define NTHREADS   128
#define A_BYTES    16384
#define SLOT_BYTES 32768
#define NSLOTS     3
#define SMEM_BYTES (1024 + NSLOTS * SLOT_BYTES)
#define NSTAGES    (HID / BK)     // 16

// ldmatrix.x4 address (SW128 layout, 128B rows): R = first row, kb = k16 byte offset
__device__ __forceinline__ uint32_t frag_addr(uint32_t base, int R, int kb, int lane) {
    const int row = R + (lane & 7) + ((lane >> 3) & 1) * 8;
    const int kc  = kb + (lane >> 4) * 16;
    const uint32_t bo = (uint32_t)(row * 128 + kc);
    return base + (bo ^ (uint32_t)((row & 7) << 4));
}

// ---------------- fp16 tensor-core GEMM with TMA loads ------------------------
template <typename OutT>
__device__ __forceinline__ void gemm_tma(const CUtensorMap* tA, const CUtensorMap* tB,
                                         int a_row0, int b_row0, OutT* __restrict__ C)
{
    extern __shared__ char smem[];
    const uint32_t sbase = smem_u32(smem);
    const uint32_t mb    = sbase;            // 3 mbarriers at +0,+8,+16
    const uint32_t slots = sbase + 1024;
    const int tid  = threadIdx.x;
    const int wid  = tid >> 5;
    const int lane = tid & 31;
    const int wm   = (wid >> 1) * 64;
    const int wn   = (wid & 1) * 64;

    if (tid == 0) {
        mbar_init(mb + 0, 1);
        mbar_init(mb + 8, 1);
        mbar_init(mb + 16, 1);
    }
    __syncthreads();

    if (tid == 0) {
#pragma unroll
        for (int s = 0; s < NSLOTS; ++s) {
            const uint32_t sl = slots + s * SLOT_BYTES;
            mbar_expect_tx(mb + s * 8, SLOT_BYTES);
            tma_load_2d(sl,           tA, s * BK, a_row0, mb + s * 8);
            tma_load_2d(sl + A_BYTES, tB, s * BK, b_row0, mb + s * 8);
        }
    }

    float acc[4][8][4];
#pragma unroll
    for (int i = 0; i < 4; ++i)
#pragma unroll
        for (int j = 0; j < 8; ++j)
#pragma unroll
            for (int r = 0; r < 4; ++r) acc[i][j][r] = 0.f;

#pragma unroll 1
    for (int t = 0; t < NSTAGES; ++t) {
        const int s = t % NSLOTS;
        mbar_wait(mb + s * 8, (t / NSLOTS) & 1);

        const uint32_t sA = slots + s * SLOT_BYTES;
        const uint32_t sB = sA + A_BYTES;

#pragma unroll
        for (int ks = 0; ks < BK / 16; ++ks) {
            const int kb = ks * 32;
            uint32_t b[8][2];
#pragma unroll
            for (int p = 0; p < 4; ++p) {
                uint32_t r[4];
                ldsm4(frag_addr(sB, wn + p * 16, kb, lane), r);
                b[2 * p][0] = r[0]; b[2 * p + 1][0] = r[1];
                b[2 * p][1] = r[2]; b[2 * p + 1][1] = r[3];
            }
#pragma unroll
            for (int fm = 0; fm < 4; ++fm) {
                uint32_t a[4];
                ldsm4(frag_addr(sA, wm + fm * 16, kb, lane), a);
#pragma unroll
                for (int fn = 0; fn < 8; ++fn)
                    mma_fp16(acc[fm][fn], a, b[fn]);
            }
        }
        __syncthreads();                       // slot s now free everywhere
        if (t + NSLOTS < NSTAGES && tid == 0) {
            mbar_expect_tx(mb + s * 8, SLOT_BYTES);
            tma_load_2d(sA,           tA, (t + NSLOTS) * BK, a_row0, mb + s * 8);
            tma_load_2d(sA + A_BYTES, tB, (t + NSLOTS) * BK, b_row0, mb + s * 8);
        }
    }

    // epilogue: register fragments -> gmem
#pragma unroll
    for (int fm = 0; fm < 4; ++fm) {
        const int r0 = a_row0 + wm + fm * 16 + (lane >> 2);
        const int cb = (b_row0 % HID);   // bn within the 1024-wide output
#pragma unroll
        for (int fn = 0; fn < 8; ++fn) {
            const int c0 = cb + wn + fn * 8 + (lane & 3) * 2;
            if constexpr (sizeof(OutT) == 2) {
                __half2 h0 = __floats2half2_rn(acc[fm][fn][0], acc[fm][fn][1]);
                __half2 h1 = __floats2half2_rn(acc[fm][fn][2], acc[fm][fn][3]);
                *(__half2*)&C[(size_t)r0 * HID + c0]       = h0;
                *(__half2*)&C[(size_t)(r0 + 8) * HID + c0] = h1;
            } else {
                float2 v0 = { acc[fm][fn][0], acc[fm][fn][1] };
                float2 v1 = { acc[fm][fn][2], acc[fm][fn][3] };
                *(float2*)&C[(size_t)r0 * HID + c0]       = v0;
                *(float2*)&C[(size_t)(r0 + 8) * HID + c0] = v1;
            }
        }
    }
}

__global__ void __launch_bounds__(NTHREADS, 2)
tc_qkv(const __grid_constant__ CUtensorMap tmA, const __grid_constant__ CUtensorMap tmB) {
    __half* C = (blockIdx.z == 0) ? g_q : (blockIdx.z == 1) ? g_k : g_v;
    gemm_tma<__half>(&tmA, &tmB,
                     blockIdx.y * BM,
                     blockIdx.z * HID + blockIdx.x * BN,   // row in 4096-row W map
                     C);
}

__global__ void __launch_bounds__(NTHREADS, 2)
tc_o(const __grid_constant__ CUtensorMap tmA, const __grid_constant__ CUtensorMap tmB,
     float* __restrict__ out) {
    gemm_tma<float>(&tmA, &tmB,
                    blockIdx.y * BM,
                    3 * HID + blockIdx.x * BN,
                    out);
}

// ---------------- fused fp32 -> fp16 conversion (x + all 4 weights) ------------
#define XCH (NTOK * HID / 4)     // float4 chunks in x
#define WCH (HID * HID / 4)      // float4 chunks per weight
__global__ void __launch_bounds__(256) conv_all(const float* __restrict__ x,
                                                const float* __restrict__ wq,
                                                const float* __restrict__ wk,
                                                const float* __restrict__ wv,
                                                const float* __restrict__ wo) {
    const size_t id = (size_t)blockIdx.x * 256 + threadIdx.x;
    const float* src;
    __half* dst;
    size_t off;
    if (id < XCH) {
        src = x; dst = g_xh; off = id;
    } else {
        const size_t wi = (id - XCH) / WCH;
        off = (id - XCH) % WCH;
        src = (wi == 0) ? wq : (wi == 1) ? wk : (wi == 2) ? wv : wo;
        dst = g_wh + wi * (size_t)HID * HID;
    }
    const float4 v = ((const float4*)src)[off];
    __half2 p0 = __floats2half2_rn(v.x, v.y);
    __half2 p1 = __floats2half2_rn(v.z, v.w);
    uint2 pk = { *(uint32_t*)&p0, *(uint32_t*)&p1 };
    *(uint2*)(dst + off * 4) = pk;
}

// ---------------- tensor-core per-token attention (validated R9) ---------------
__global__ void __launch_bounds__(256) attn_kernel() {
    __shared__ __align__(128) char sm[8 * 3 * 2048];
    const uint32_t sbase = smem_u32(sm);
    const int tid  = threadIdx.x;
    const int lane = tid & 31;
    const int wid  = tid >> 5;
    const size_t tok0 = (size_t)blockIdx.x * 8;

#pragma unroll
    for (int j = 0; j < 12; ++j) {
        const int id   = tid + j * 256;
        const int w    = id / 384;
        const int rem  = id - w * 384;
        const int tile = rem >> 7;
        const int c    = rem & 127;
        const int row  = c >> 3;
        const int c8   = c & 7;
        const __half* src = (tile == 0 ? g_q : tile == 1 ? g_k : g_v)
                          + (tok0 + w) * HID + row * HDIM + c8 * 8;
        const uint32_t bo = (uint32_t)(row * 128 + c8 * 16);
        const uint32_t sw = bo ^ (uint32_t)((row & 7) << 4);
        cp_async16(sbase + (uint32_t)(w * 3 + tile) * 2048 + sw, src);
    }
    cp_commit();
    cp_wait<0>();
    __syncthreads();

    const uint32_t qb = sbase + (uint32_t)(wid * 3 + 0) * 2048;
    const uint32_t kb = sbase + (uint32_t)(wid * 3 + 1) * 2048;
    const uint32_t vb = sbase + (uint32_t)(wid * 3 + 2) * 2048;

    float sc[2][4];
#pragma unroll
    for (int i = 0; i < 2; ++i)
#pragma unroll
        for (int r = 0; r < 4; ++r) sc[i][r] = 0.f;

#pragma unroll
    for (int s = 0; s < 4; ++s) {
        uint32_t a[4], b[4];
        ldsm4(frag_addr(qb, 0, s * 32, lane), a);
        ldsm4(frag_addr(kb, 0, s * 32, lane), b);
        uint32_t b0[2] = { b[0], b[2] };
        uint32_t b1[2] = { b[1], b[3] };
        mma_fp16(sc[0], a, b0);
        mma_fp16(sc[1], a, b1);
    }

    float mlo = fmaxf(fmaxf(sc[0][0], sc[0][1]), fmaxf(sc[1][0], sc[1][1]));
    float mhi = fmaxf(fmaxf(sc[0][2], sc[0][3]), fmaxf(sc[1][2], sc[1][3]));
#pragma unroll
    for (int off = 1; off <= 2; off <<= 1) {
        mlo = fmaxf(mlo, __shfl_xor_sync(0xffffffffu, mlo, off));
        mhi = fmaxf(mhi, __shfl_xor_sync(0xffffffffu, mhi, off));
    }
    float plo[4], phi[4];
    plo[0] = __expf(0.125f * (sc[0][0] - mlo));
    plo[1] = __expf(0.125f * (sc[0][1] - mlo));
    plo[2] = __expf(0.125f * (sc[1][0] - mlo));
    plo[3] = __expf(0.125f * (sc[1][1] - mlo));
    phi[0] = __expf(0.125f * (sc[0][2] - mhi));
    phi[1] = __expf(0.125f * (sc[0][3] - mhi));
    phi[2] = __expf(0.125f * (sc[1][2] - mhi));
    phi[3] = __expf(0.125f * (sc[1][3] - mhi));
    float slo = plo[0] + plo[1] + plo[2] + plo[3];
    float shi = phi[0] + phi[1] + phi[2] + phi[3];
#pragma unroll
    for (int off = 1; off <= 2; off <<= 1) {
        slo += __shfl_xor_sync(0xffffffffu, slo, off);
        shi += __shfl_xor_sync(0xffffffffu, shi, off);
    }
    const float rlo = 1.f / slo, rhi = 1.f / shi;

    uint32_t pa[4];
    {
        __half2 h;
        h = __floats2half2_rn(plo[0] * rlo, plo[1] * rlo); pa[0] = *(uint32_t*)&h;
        h = __floats2half2_rn(phi[0] * rhi, phi[1] * rhi); pa[1] = *(uint32_t*)&h;
        h = __floats2half2_rn(plo[2] * rlo, plo[3] * rlo); pa[2] = *(uint32_t*)&h;
        h = __floats2half2_rn(phi[2] * rhi, phi[3] * rhi); pa[3] = *(uint32_t*)&h;
    }

    float o[8][4];
#pragma unroll
    for (int j = 0; j < 8; ++j)
#pragma unroll
        for (int r = 0; r < 4; ++r) o[j][r] = 0.f;

#pragma unroll
    for (int j2 = 0; j2 < 4; ++j2) {
        uint32_t b[4];
        ldsm4t(frag_addr(vb, 0, j2 * 32, lane), b);
        uint32_t b0[2] = { b[0], b[1] };
        uint32_t b1[2] = { b[2], b[3] };
        mma_fp16(o[2 * j2],     pa, b0);
        mma_fp16(o[2 * j2 + 1], pa, b1);
    }

    char* stp = sm + wid * 3 * 2048;
    {
        const int r  = lane >> 2;
        const int cb = (lane & 3) * 4;
#pragma unroll
        for (int j = 0; j < 8; ++j) {
            __half2 lo2 = __floats2half2_rn(o[j][0], o[j][1]);
            __half2 hi2 = __floats2half2_rn(o[j][2], o[j][3]);
            *(__half2*)(stp + r * 144 + j * 16 + cb)       = lo2;
            *(__half2*)(stp + (r + 8) * 144 + j * 16 + cb) = hi2;
        }
    }
    __syncwarp();
    {
        __half* gdst = g_ah + (tok0 + wid) * HID;
#pragma unroll
        for (int l = 0; l < 4; ++l) {
            const int id  = lane + l * 32;
            const int row = id >> 3;
            const int c8  = id & 7;
            const uint4 v = *(const uint4*)(stp + row * 144 + c8 * 16);
            *(uint4*)(gdst + row * HDIM + c8 * 8) = v;
        }
    }
}

// ---------------- host: tensor-map creation + launch ---------------------------
typedef CUresult (*PFN_encodeTiled)(CUtensorMap*, CUtensorMapDataType, cuuint32_t,
                                    void*, const cuuint64_t*, const cuuint64_t*,
                                    const cuuint32_t*, const cuuint32_t*,
                                    CUtensorMapInterleave, CUtensorMapSwizzle,
                                    CUtensorMapL2promotion, CUtensorMapFloatOOBfill);

static void make_map(PFN_encodeTiled enc, CUtensorMap* tm, void* base, uint64_t rows) {
    cuuint64_t dims[2]    = { (cuuint64_t)HID, (cuuint64_t)rows };
    cuuint64_t strides[1] = { (cuuint64_t)(HID * sizeof(__half)) };
    cuuint32_t box[2]     = { BK, BM };      // 64 fp16 = 128B (SW128 max), 128 rows
    cuuint32_t estr[2]    = { 1, 1 };
    enc(tm, CU_TENSOR_MAP_DATA_TYPE_FLOAT16, 2, base, dims, strides, box, estr,
        CU_TENSOR_MAP_INTERLEAVE_NONE, CU_TENSOR_MAP_SWIZZLE_128B,
        CU_TENSOR_MAP_L2_PROMOTION_L2_128B, CU_TENSOR_MAP_FLOAT_OOB_FILL_NONE);
}

extern "C" void kernel_launch(void* const* d_in, const int* in_sizes, int n_in,
                              void* d_out, int out_size)
{
    const float* x  = (const float*)d_in[0];
    const float* wq = (const float*)d_in[1];
    const float* wk = (const float*)d_in[2];
    const float* wv = (const float*)d_in[3];
    const float* wo = (const float*)d_in[4];
    float* out = (float*)d_out;

    void* fn = nullptr;
#if CUDART_VERSION >= 12050
    cudaDriverEntryPointQueryResult qr;
    cudaGetDriverEntryPointByVersion("cuTensorMapEncodeTiled", &fn, 12000,
                                     cudaEnableDefault, &qr);
#else
    cudaGetDriverEntryPoint("cuTensorMapEncodeTiled", &fn, cudaEnableDefault, nullptr);
#endif
    PFN_encodeTiled enc = (PFN_encodeTiled)fn;

    void *pxh, *pwh, *pah;
    cudaGetSymbolAddress(&pxh, g_xh);
    cudaGetSymbolAddress(&pwh, g_wh);
    cudaGetSymbolAddress(&pah, g_ah);

    alignas(64) CUtensorMap tmX, tmW, tmA;
    make_map(enc, &tmX, pxh, NTOK);
    make_map(enc, &tmW, pwh, 4 * HID);
    make_map(enc, &tmA, pah, NTOK);

    cudaFuncSetAttribute(tc_qkv, cudaFuncAttributeMaxDynamicSharedMemorySize, SMEM_BYTES);
    cudaFuncSetAttribute(tc_o,   cudaFuncAttributeMaxDynamicSharedMemorySize, SMEM_BYTES);

    conv_all<<<(XCH + 4 * WCH) / 256, 256>>>(x, wq, wk, wv, wo);

    dim3 gqkv(HID / BN, NTOK / BM, 3);     // (8, 128, 3)
    tc_qkv<<<gqkv, NTHREADS, SMEM_BYTES>>>(tmX, tmW);

    attn_kernel<<<NTOK / 8, 256>>>();

    dim3 go(HID / BN, NTOK / BM, 1);       // (8, 128, 1)
    tc_o<<<go, NTHREADS, SMEM_BYTES>>>(tmA, tmW, out);
}